// round 1
// baseline (speedup 1.0000x reference)
#include <cuda_runtime.h>
#include <math.h>

// Problem constants
//  x: (8, 256, 64, 64)  ->  out: (8, 256, 128, 128)
//  M = 8*64*64 = 32768 pixels, K1 = 256*9 = 2304, K2 = 256*4 = 1024
#define M_TOT 32768

// ---------------- scratch (__device__ globals; no allocation) ----------------
__device__ float g_col[2304u * 32768u];      // im2col(x), (K, M)      302 MB
__device__ float g_v[2304u * 32768u];        // deform samples, (K, M) 302 MB
__device__ float g_offmask[27u * 32768u];    // offsets+mask raw, (27, M)
__device__ float g_Bom[27 * 2304];           // packed offset/mask weights (N,K)
__device__ float g_biasom[27];               // packed biases
__device__ float g_h1[8u * 256u * 4096u];    // stage-1 output NCHW 64x64 (33.5 MB)
__device__ float g_u[4u * 1024u * 32768u];   // per-parity gather, (K2, M)  537 MB
__device__ float g_B2[4u * 256u * 1024u];    // per-parity convT weights (N, K2)

// ---------------- im2col of x: g_col[kidx][m], kidx = c*9 + ty*3+tx ----------
__global__ void im2col_kernel(const float* __restrict__ x) {
    int m = blockIdx.x * 256 + threadIdx.x;
    int kidx = blockIdx.y;
    int c = kidx / 9, t = kidx % 9, ty = t / 3, tx = t % 3;
    int b = m >> 12, pix = m & 4095, h = pix >> 6, w = pix & 63;
    int y = h + ty - 1, xx = w + tx - 1;
    float v = 0.f;
    if (y >= 0 && y < 64 && xx >= 0 && xx < 64)
        v = x[(((size_t)(b * 256 + c)) << 12) + (y << 6) + xx];
    g_col[(size_t)kidx * M_TOT + m] = v;
}

// ---------------- pack offset(18)+mask(9) conv weights/bias -------------------
__global__ void prepack_om_kernel(const float* __restrict__ w_off,
                                  const float* __restrict__ b_off,
                                  const float* __restrict__ w_mod,
                                  const float* __restrict__ b_mod) {
    int i = blockIdx.x * 256 + threadIdx.x;
    const int tot = 27 * 2304;
    if (i < 18 * 2304)       g_Bom[i] = w_off[i];
    else if (i < tot)        g_Bom[i] = w_mod[i - 18 * 2304];
    if (i >= tot && i < tot + 27) {
        int n = i - tot;
        g_biasom[n] = (n < 18) ? b_off[n] : b_mod[n - 18];
    }
}

// ---------------- pack conv-transpose weights per parity ----------------------
// g_B2[p][n][k], k = c*4 + (ty*2+tx);  kh/kw selected by (parity, tap)
__global__ void prepack_B2_kernel(const float* __restrict__ w_up) {
    int i = blockIdx.x * 256 + threadIdx.x;   // over 4*256*1024 = 2^20
    int k = i & 1023, n = (i >> 10) & 255, p = i >> 18;
    int c = k >> 2, t = k & 3, ty = t >> 1, tx = t & 1;
    int py = p >> 1, px = p & 1;
    int kh = py ? (ty ? 2 : 0) : (ty ? 3 : 1);
    int kw = px ? (tx ? 2 : 0) : (tx ? 3 : 1);
    g_B2[i] = w_up[(c << 12) + (n << 4) + (kh << 2) + kw];
}

// ---------------- generic tiled fp32 GEMM: C(M,N) = A(K,M)^T * B(N,K)^T ------
// EPI 0: +bias, store (N,M) planes (offset/mask)
// EPI 1: BN1+ReLU, store NCHW 64x64 (g_h1)
// EPI 2: BN2+ReLU, scatter to d_out at parity (2i+py, 2j+px), 128x128
template <int EPI>
__global__ __launch_bounds__(256) void gemm_kernel(
    const float* __restrict__ A, const float* __restrict__ B,
    float* __restrict__ C, int N, int K,
    const float* __restrict__ bias,
    const float* __restrict__ gam, const float* __restrict__ bet,
    const float* __restrict__ mea, const float* __restrict__ var,
    int parity) {
    __shared__ float As[16][128];
    __shared__ float Bs[16][64];
    int tid = threadIdx.x;
    int n0 = blockIdx.x * 64, m0 = blockIdx.y * 128;
    int tx = tid & 15, ty = tid >> 4;
    int bn = tid >> 2, bk4 = (tid & 3) << 2;

    float acc[8][4];
#pragma unroll
    for (int i = 0; i < 8; i++)
#pragma unroll
        for (int j = 0; j < 4; j++) acc[i][j] = 0.f;

    for (int k0 = 0; k0 < K; k0 += 16) {
#pragma unroll
        for (int r = 0; r < 2; r++) {
            int idx = tid + r * 256;
            int kr = idx >> 5, mc = (idx & 31) << 2;
            *(float4*)&As[kr][mc] =
                *(const float4*)&A[(size_t)(k0 + kr) * M_TOT + m0 + mc];
        }
        {
            float4 bv = make_float4(0.f, 0.f, 0.f, 0.f);
            if (n0 + bn < N)
                bv = *(const float4*)&B[(size_t)(n0 + bn) * K + k0 + bk4];
            Bs[bk4 + 0][bn] = bv.x; Bs[bk4 + 1][bn] = bv.y;
            Bs[bk4 + 2][bn] = bv.z; Bs[bk4 + 3][bn] = bv.w;
        }
        __syncthreads();
#pragma unroll
        for (int kk = 0; kk < 16; kk++) {
            float a[8], bb[4];
            *(float4*)&a[0] = *(float4*)&As[kk][ty * 8];
            *(float4*)&a[4] = *(float4*)&As[kk][ty * 8 + 4];
            *(float4*)&bb[0] = *(float4*)&Bs[kk][tx * 4];
#pragma unroll
            for (int i = 0; i < 8; i++)
#pragma unroll
                for (int j = 0; j < 4; j++) acc[i][j] += a[i] * bb[j];
        }
        __syncthreads();
    }

#pragma unroll
    for (int j = 0; j < 4; j++) {
        int n = n0 + tx * 4 + j;
        if (EPI == 0 && n >= N) continue;
        float sc = 1.f, sh = 0.f;
        if (EPI == 0) {
            sh = bias[n];
        } else {
            float s = gam[n] * rsqrtf(var[n] + 1e-5f);
            sc = s;
            sh = bet[n] - mea[n] * s;
        }
#pragma unroll
        for (int i = 0; i < 8; i++) {
            int m = m0 + ty * 8 + i;
            float v = acc[i][j] * sc + sh;
            if (EPI != 0) v = fmaxf(v, 0.f);
            if (EPI == 0) {
                C[(size_t)n * M_TOT + m] = v;
            } else if (EPI == 1) {
                int b = m >> 12, pix = m & 4095;
                C[(((size_t)(b * 256 + n)) << 12) + pix] = v;
            } else {
                int b = m >> 12, pix = m & 4095, i2 = pix >> 6, j2 = pix & 63;
                int py = parity >> 1, px = parity & 1;
                C[(((size_t)((b * 256 + n) * 128 + 2 * i2 + py)) << 7) +
                  2 * j2 + px] = v;
            }
        }
    }
}

// ---------------- modulated bilinear sampling: g_v[c*9+k][m] -----------------
__global__ void build_v_kernel(const float* __restrict__ x) {
    int m = blockIdx.x * 256 + threadIdx.x;
    int k = blockIdx.y;
    int b = m >> 12, pix = m & 4095, h = pix >> 6, w = pix & 63;
    float oy = g_offmask[(size_t)(2 * k) * M_TOT + m];
    float ox = g_offmask[(size_t)(2 * k + 1) * M_TOT + m];
    float mr = g_offmask[(size_t)(18 + k) * M_TOT + m];
    float mask = 2.f / (1.f + expf(-mr));
    int ky = k / 3, kx = k % 3;
    float py = (float)(h - 1 + ky) + oy;
    float px = (float)(w - 1 + kx) + ox;
    float y0f = floorf(py), x0f = floorf(px);
    float wy1 = py - y0f, wx1 = px - x0f;
    float wy0 = 1.f - wy1, wx0 = 1.f - wx1;
    int y0 = (int)y0f, x0 = (int)x0f;
    int y1 = y0 + 1, x1 = x0 + 1;
    bool vy0 = (y0 >= 0 && y0 < 64), vy1 = (y1 >= 0 && y1 < 64);
    bool vx0 = (x0 >= 0 && x0 < 64), vx1 = (x1 >= 0 && x1 < 64);
    int yc0 = min(max(y0, 0), 63), yc1 = min(max(y1, 0), 63);
    int xc0 = min(max(x0, 0), 63), xc1 = min(max(x1, 0), 63);
    int o00 = (yc0 << 6) + xc0, o01 = (yc0 << 6) + xc1;
    int o10 = (yc1 << 6) + xc0, o11 = (yc1 << 6) + xc1;
    float w00 = wy0 * wx0 * ((vy0 && vx0) ? mask : 0.f);
    float w01 = wy0 * wx1 * ((vy0 && vx1) ? mask : 0.f);
    float w10 = wy1 * wx0 * ((vy1 && vx0) ? mask : 0.f);
    float w11 = wy1 * wx1 * ((vy1 && vx1) ? mask : 0.f);
    const float* xb = x + ((size_t)b << 20);
    for (int c = 0; c < 256; c++) {
        const float* xc = xb + (c << 12);
        float v = w00 * xc[o00] + w01 * xc[o01] + w10 * xc[o10] + w11 * xc[o11];
        g_v[(size_t)(c * 9 + k) * M_TOT + m] = v;
    }
}

// ---------------- conv-transpose gather per parity: g_u[p][c*4+t][m] ---------
__global__ void build_u_kernel() {
    int m = blockIdx.x * 256 + threadIdx.x;
    int p = blockIdx.y;
    int py = p >> 1, px = p & 1;
    int b = m >> 12, pix = m & 4095, i = pix >> 6, j = pix & 63;
    int r0 = py ? i + 1 : i;       // tap ty=0
    int r1 = py ? i : i - 1;       // tap ty=1
    int c0 = px ? j + 1 : j;
    int c1 = px ? j : j - 1;
    bool vr0 = (r0 >= 0 && r0 < 64), vr1 = (r1 >= 0 && r1 < 64);
    bool vc0 = (c0 >= 0 && c0 < 64), vc1 = (c1 >= 0 && c1 < 64);
    float* up = g_u + (size_t)p * 1024u * M_TOT;
    for (int c = 0; c < 256; c++) {
        const float* h1c = g_h1 + (((size_t)(b * 256 + c)) << 12);
        float v00 = (vr0 && vc0) ? h1c[(r0 << 6) + c0] : 0.f;
        float v01 = (vr0 && vc1) ? h1c[(r0 << 6) + c1] : 0.f;
        float v10 = (vr1 && vc0) ? h1c[(r1 << 6) + c0] : 0.f;
        float v11 = (vr1 && vc1) ? h1c[(r1 << 6) + c1] : 0.f;
        size_t base = (size_t)(c * 4) * M_TOT + m;
        up[base + 0 * M_TOT] = v00;
        up[base + 1 * M_TOT] = v01;
        up[base + 2 * M_TOT] = v10;
        up[base + 3 * M_TOT] = v11;
    }
}

// -----------------------------------------------------------------------------
extern "C" void kernel_launch(void* const* d_in, const int* in_sizes, int n_in,
                              void* d_out, int out_size) {
    const float* x      = (const float*)d_in[0];
    const float* w_off  = (const float*)d_in[1];
    const float* b_off  = (const float*)d_in[2];
    const float* w_mod  = (const float*)d_in[3];
    const float* b_mod  = (const float*)d_in[4];
    const float* w_reg  = (const float*)d_in[5];
    const float* bn1_g  = (const float*)d_in[6];
    const float* bn1_b  = (const float*)d_in[7];
    const float* bn1_m  = (const float*)d_in[8];
    const float* bn1_v  = (const float*)d_in[9];
    const float* w_up   = (const float*)d_in[10];
    const float* bn2_g  = (const float*)d_in[11];
    const float* bn2_b  = (const float*)d_in[12];
    const float* bn2_m  = (const float*)d_in[13];
    const float* bn2_v  = (const float*)d_in[14];
    float* out = (float*)d_out;

    float *col, *v, *om, *Bom, *biasom, *h1, *u, *B2;
    cudaGetSymbolAddress((void**)&col,    g_col);
    cudaGetSymbolAddress((void**)&v,      g_v);
    cudaGetSymbolAddress((void**)&om,     g_offmask);
    cudaGetSymbolAddress((void**)&Bom,    g_Bom);
    cudaGetSymbolAddress((void**)&biasom, g_biasom);
    cudaGetSymbolAddress((void**)&h1,     g_h1);
    cudaGetSymbolAddress((void**)&u,      g_u);
    cudaGetSymbolAddress((void**)&B2,     g_B2);

    // weight packing (cheap)
    prepack_om_kernel<<<(27 * 2304 + 27 + 255) / 256, 256>>>(w_off, b_off,
                                                             w_mod, b_mod);
    prepack_B2_kernel<<<4096, 256>>>(w_up);

    // stage 0: offset/mask conv = im2col + GEMM (N=27)
    im2col_kernel<<<dim3(128, 2304), 256>>>(x);
    gemm_kernel<0><<<dim3(1, 256), 256>>>(col, Bom, om, 27, 2304, biasom,
                                          nullptr, nullptr, nullptr, nullptr, 0);

    // stage 1: modulated bilinear sampling + deform GEMM (+BN1+ReLU)
    build_v_kernel<<<dim3(128, 9), 256>>>(x);
    gemm_kernel<1><<<dim3(4, 256), 256>>>(v, w_reg, h1, 256, 2304, nullptr,
                                          bn1_g, bn1_b, bn1_m, bn1_v, 0);

    // stage 2: conv-transpose as 4 parity GEMMs (+BN2+ReLU, scatter to d_out)
    build_u_kernel<<<dim3(128, 4), 256>>>();
    for (int p = 0; p < 4; p++) {
        gemm_kernel<2><<<dim3(4, 256), 256>>>(
            u + (size_t)p * 1024u * M_TOT, B2 + (size_t)p * 256u * 1024u, out,
            256, 1024, nullptr, bn2_g, bn2_b, bn2_m, bn2_v, p);
    }
}

// round 4
// speedup vs baseline: 1.0392x; 1.0392x over previous
#include <cuda_runtime.h>
#include <cuda_bf16.h>
#include <math.h>
#include <stdint.h>

#define M_TOT 32768
#define K1 2304
#define K2 1024

// ----------------------------- scratch ---------------------------------------
__device__ uint32_t g_col[(size_t)K1 * M_TOT];     // im2col(x), packed bf16 hi|lo<<16, (K1, M)
__device__ uint32_t g_v[(size_t)K1 * M_TOT];       // deform samples, packed, (K1, M)
__device__ uint32_t g_u[(size_t)4 * K2 * M_TOT];   // convT gather per parity, packed
__device__ float    g_offmask[32u * M_TOT];        // offset/mask conv out (27 used rows)
__device__ float    g_h1[(size_t)8 * 256 * 4096];  // stage-1 output NCHW 64x64
__device__ __nv_bfloat16 g_Wh[256 * K1],  g_Wl[256 * K1];    // w_reg split (N,K)
__device__ __nv_bfloat16 g_Bomh[32 * K1], g_Boml[32 * K1];   // offset+mask weights (pad 32)
__device__ float    g_biasom[32];
__device__ __nv_bfloat16 g_B2h[4 * 256 * K2], g_B2l[4 * 256 * K2]; // convT per-parity (N,K)

// ----------------------------- helpers ---------------------------------------
__device__ __forceinline__ uint32_t smem_u32(const void* p) {
    uint32_t a;
    asm("{ .reg .u64 t; cvta.to.shared.u64 t, %1; cvt.u32.u64 %0, t; }" : "=r"(a) : "l"(p));
    return a;
}
__device__ __forceinline__ void ldsm4(uint32_t* r, uint32_t addr) {
    asm volatile("ldmatrix.sync.aligned.m8n8.x4.shared.b16 {%0,%1,%2,%3}, [%4];"
                 : "=r"(r[0]), "=r"(r[1]), "=r"(r[2]), "=r"(r[3]) : "r"(addr));
}
__device__ __forceinline__ void mma16816(float* c, const uint32_t* a, const uint32_t* b) {
    asm volatile(
        "mma.sync.aligned.m16n8k16.row.col.f32.bf16.bf16.f32 "
        "{%0,%1,%2,%3}, {%4,%5,%6,%7}, {%8,%9}, {%0,%1,%2,%3};"
        : "+f"(c[0]), "+f"(c[1]), "+f"(c[2]), "+f"(c[3])
        : "r"(a[0]), "r"(a[1]), "r"(a[2]), "r"(a[3]), "r"(b[0]), "r"(b[1]));
}
__device__ __forceinline__ uint32_t packbf(float a) {
    __nv_bfloat16 h = __float2bfloat16(a);
    float hf = __bfloat162float(h);
    __nv_bfloat16 l = __float2bfloat16(a - hf);
    return (uint32_t)__bfloat16_as_ushort(h) | ((uint32_t)__bfloat16_as_ushort(l) << 16);
}
__device__ __forceinline__ void splitbf(float a, __nv_bfloat16& h, __nv_bfloat16& l) {
    h = __float2bfloat16(a);
    l = __float2bfloat16(a - __bfloat162float(h));
}

// ----------------------------- weight packing --------------------------------
__global__ void pack_w_kernel(const float* __restrict__ w_reg, const float* __restrict__ w_off,
                              const float* __restrict__ b_off, const float* __restrict__ w_mod,
                              const float* __restrict__ b_mod, const float* __restrict__ w_up) {
    int i = blockIdx.x * 256 + threadIdx.x;
    if (i < 256 * K1) splitbf(w_reg[i], g_Wh[i], g_Wl[i]);
    if (i < 32 * K1) {
        int n = i / K1;
        float v = 0.f;
        if (n < 18) v = w_off[i];
        else if (n < 27) v = w_mod[i - 18 * K1];
        splitbf(v, g_Bomh[i], g_Boml[i]);
    }
    if (i < 32) g_biasom[i] = (i < 18) ? b_off[i] : ((i < 27) ? b_mod[i - 18] : 0.f);
    if (i < 4 * 256 * K2) {
        int k = i & 1023, n = (i >> 10) & 255, p = i >> 18;
        int c = k >> 2, t = k & 3, ty = t >> 1, tx = t & 1;
        int py = p >> 1, px = p & 1;
        int kh = py ? (ty ? 2 : 0) : (ty ? 3 : 1);
        int kw = px ? (tx ? 2 : 0) : (tx ? 3 : 1);
        splitbf(w_up[(c << 12) + (n << 4) + (kh << 2) + kw], g_B2h[i], g_B2l[i]);
    }
}

// ----------------------------- im2col ----------------------------------------
__global__ void im2col_kernel(const float* __restrict__ x) {
    int m = blockIdx.x * 256 + threadIdx.x;
    int kidx = blockIdx.y;
    int c = kidx / 9, t = kidx % 9, ty = t / 3, tx = t % 3;
    int b = m >> 12, pix = m & 4095, h = pix >> 6, w = pix & 63;
    int y = h + ty - 1, xx = w + tx - 1;
    float v = 0.f;
    if (y >= 0 && y < 64 && xx >= 0 && xx < 64)
        v = x[(((size_t)(b * 256 + c)) << 12) + (y << 6) + xx];
    g_col[(size_t)kidx * M_TOT + m] = packbf(v);
}

// ----------------------------- deform sampling -------------------------------
__global__ void build_v_kernel(const float* __restrict__ x) {
    int m = blockIdx.x * 256 + threadIdx.x;
    int k = blockIdx.y;
    int b = m >> 12, pix = m & 4095, h = pix >> 6, w = pix & 63;
    float oy = g_offmask[(size_t)(2 * k) * M_TOT + m];
    float ox = g_offmask[(size_t)(2 * k + 1) * M_TOT + m];
    float mr = g_offmask[(size_t)(18 + k) * M_TOT + m];
    float mask = 2.f / (1.f + expf(-mr));
    int ky = k / 3, kx = k % 3;
    float py = (float)(h - 1 + ky) + oy;
    float px = (float)(w - 1 + kx) + ox;
    float y0f = floorf(py), x0f = floorf(px);
    float wy1 = py - y0f, wx1 = px - x0f;
    float wy0 = 1.f - wy1, wx0 = 1.f - wx1;
    int y0 = (int)y0f, x0 = (int)x0f, y1 = y0 + 1, x1 = x0 + 1;
    bool vy0 = (y0 >= 0 && y0 < 64), vy1 = (y1 >= 0 && y1 < 64);
    bool vx0 = (x0 >= 0 && x0 < 64), vx1 = (x1 >= 0 && x1 < 64);
    int yc0 = min(max(y0, 0), 63), yc1 = min(max(y1, 0), 63);
    int xc0 = min(max(x0, 0), 63), xc1 = min(max(x1, 0), 63);
    int o00 = (yc0 << 6) + xc0, o01 = (yc0 << 6) + xc1;
    int o10 = (yc1 << 6) + xc0, o11 = (yc1 << 6) + xc1;
    float w00 = wy0 * wx0 * ((vy0 && vx0) ? mask : 0.f);
    float w01 = wy0 * wx1 * ((vy0 && vx1) ? mask : 0.f);
    float w10 = wy1 * wx0 * ((vy1 && vx0) ? mask : 0.f);
    float w11 = wy1 * wx1 * ((vy1 && vx1) ? mask : 0.f);
    const float* xb = x + ((size_t)b << 20);
    for (int c = 0; c < 256; c++) {
        const float* xc = xb + (c << 12);
        float v = w00 * xc[o00] + w01 * xc[o01] + w10 * xc[o10] + w11 * xc[o11];
        g_v[(size_t)(c * 9 + k) * M_TOT + m] = packbf(v);
    }
}

// ----------------------------- convT gather ----------------------------------
__global__ void build_u_kernel() {
    int m = blockIdx.x * 256 + threadIdx.x;
    int p = blockIdx.y;
    int py = p >> 1, px = p & 1;
    int b = m >> 12, pix = m & 4095, i = pix >> 6, j = pix & 63;
    int r0 = py ? i + 1 : i;
    int r1 = py ? i : i - 1;
    int c0 = px ? j + 1 : j;
    int c1 = px ? j : j - 1;
    bool vr0 = (r0 >= 0 && r0 < 64), vr1 = (r1 >= 0 && r1 < 64);
    bool vc0 = (c0 >= 0 && c0 < 64), vc1 = (c1 >= 0 && c1 < 64);
    uint32_t* up = g_u + (size_t)p * K2 * M_TOT;
    for (int c = 0; c < 256; c++) {
        const float* h1c = g_h1 + (((size_t)(b * 256 + c)) << 12);
        float v00 = (vr0 && vc0) ? h1c[(r0 << 6) + c0] : 0.f;
        float v01 = (vr0 && vc1) ? h1c[(r0 << 6) + c1] : 0.f;
        float v10 = (vr1 && vc0) ? h1c[(r1 << 6) + c0] : 0.f;
        float v11 = (vr1 && vc1) ? h1c[(r1 << 6) + c1] : 0.f;
        size_t base = (size_t)(c * 4) * M_TOT + m;
        up[base + 0 * M_TOT] = packbf(v00);
        up[base + 1 * M_TOT] = packbf(v01);
        up[base + 2 * M_TOT] = packbf(v10);
        up[base + 3 * M_TOT] = packbf(v11);
    }
}

// ----------------------------- warp-MMA GEMM ---------------------------------
// C(M=32768, N) = A(K,M)^T x B(N,K)^T, bf16 split (hh + hl + lh), fp32 accum.
// A packed u32 (hi|lo). SMEM rows padded to 80B for conflict-free ldmatrix.
template <int NTILE, int EPI>
__global__ __launch_bounds__(256) void mma_gemm(
    const uint32_t* __restrict__ A, const __nv_bfloat16* __restrict__ Bhg,
    const __nv_bfloat16* __restrict__ Blg, float* __restrict__ C, int K,
    const float* __restrict__ p0, const float* __restrict__ p1,
    const float* __restrict__ p2, const float* __restrict__ p3) {
    constexpr int WN = (NTILE >= 128) ? 4 : 2;     // warps along N
    constexpr int WM = 8 / WN;                     // warps along M
    constexpr int WARP_M = 128 / WM;               // 64 or 32
    constexpr int WARP_N = NTILE / WN;             // 32 or 16
    constexpr int MT = WARP_M / 16;                // m16 tiles per warp
    constexpr int NTG = WARP_N / 16;               // B ldmatrix.x4 groups
    constexpr int NT = NTG * 2;                    // n8 tiles per warp
    constexpr int AS = 128 * 80;                   // one A plane bytes
    constexpr int BS = NTILE * 80;
    constexpr int BN4 = NTILE * 4;                 // 16B chunks per B plane
    constexpr int BJ = (BN4 + 255) / 256;

    extern __shared__ char sb[];
    char* sAh = sb;
    char* sAl = sb + AS;
    char* sBh = sb + 2 * AS;
    char* sBl = sb + 2 * AS + BS;
    uint32_t sbase = smem_u32(sb);

    int t = threadIdx.x, warp = t >> 5, lane = t & 31;
    int mw = (warp / WN) * WARP_M;
    int nw = (warp % WN) * WARP_N;
    int m0 = blockIdx.x * 128;
    int nbase = blockIdx.y * NTILE;
    int par = blockIdx.z;
    const uint32_t* Ag = A + (size_t)par * K * M_TOT + m0;
    // FIX (R3 bug): offset B pointers by the CTA's N-tile base.
    const __nv_bfloat16* Bh = Bhg + (size_t)par * 256 * K + (size_t)nbase * K;
    const __nv_bfloat16* Bl = Blg + (size_t)par * 256 * K + (size_t)nbase * K;

    // ldmatrix lane addressing
    int a_row = lane & 15, a_kh = (lane >> 4) << 3;
    int b_row = (lane & 7) | ((lane >> 4) << 3);
    int b_kh = ((lane >> 3) & 1) << 3;
    uint32_t aAddrH = sbase + (uint32_t)((mw + a_row) * 80 + a_kh * 2);
    uint32_t aAddrL = aAddrH + AS;
    uint32_t bAddrH = sbase + 2 * AS + (uint32_t)((nw + b_row) * 80 + b_kh * 2);
    uint32_t bAddrL = bAddrH + BS;

    float acc[MT][NT][4];
#pragma unroll
    for (int i = 0; i < MT; i++)
#pragma unroll
        for (int j = 0; j < NT; j++)
#pragma unroll
            for (int e = 0; e < 4; e++) acc[i][j][e] = 0.f;

    float4 areg[4], bregh[BJ], bregl[BJ];
    int nch = K >> 5;

    // prefetch chunk 0
    {
#pragma unroll
        for (int i = 0; i < 4; i++) {
            int idx = t + i * 256;
            int k = idx >> 5, mq = (idx & 31) << 2;
            areg[i] = *(const float4*)(Ag + (size_t)k * M_TOT + mq);
        }
#pragma unroll
        for (int j = 0; j < BJ; j++) {
            int i = t + j * 256;
            if (i < BN4) {
                int n = i >> 2, kq = i & 3;
                bregh[j] = *(const float4*)(Bh + (size_t)n * K + kq * 8);
                bregl[j] = *(const float4*)(Bl + (size_t)n * K + kq * 8);
            }
        }
    }

    for (int c = 0; c < nch; c++) {
        __syncthreads();
        // store staged regs to SMEM (transpose A)
#pragma unroll
        for (int i = 0; i < 4; i++) {
            int idx = t + i * 256;
            int k = idx >> 5, mq = (idx & 31) << 2;
            const uint32_t* w = (const uint32_t*)&areg[i];
#pragma unroll
            for (int q = 0; q < 4; q++) {
                int off = (mq + q) * 80 + k * 2;
                *(uint16_t*)(sAh + off) = (uint16_t)w[q];
                *(uint16_t*)(sAl + off) = (uint16_t)(w[q] >> 16);
            }
        }
#pragma unroll
        for (int j = 0; j < BJ; j++) {
            int i = t + j * 256;
            if (i < BN4) {
                int n = i >> 2, kq = i & 3;
                *(float4*)(sBh + n * 80 + kq * 16) = bregh[j];
                *(float4*)(sBl + n * 80 + kq * 16) = bregl[j];
            }
        }
        __syncthreads();
        // prefetch next chunk
        if (c + 1 < nch) {
            size_t k0 = (size_t)(c + 1) << 5;
#pragma unroll
            for (int i = 0; i < 4; i++) {
                int idx = t + i * 256;
                int k = idx >> 5, mq = (idx & 31) << 2;
                areg[i] = *(const float4*)(Ag + (k0 + k) * M_TOT + mq);
            }
#pragma unroll
            for (int j = 0; j < BJ; j++) {
                int i = t + j * 256;
                if (i < BN4) {
                    int n = i >> 2, kq = i & 3;
                    bregh[j] = *(const float4*)(Bh + (size_t)n * K + k0 + kq * 8);
                    bregl[j] = *(const float4*)(Bl + (size_t)n * K + k0 + kq * 8);
                }
            }
        }
        // MMA on current chunk (2 k16 steps)
#pragma unroll
        for (int ks = 0; ks < 2; ks++) {
            int kb = ks * 32;  // 16 elems * 2B
            uint32_t ah[MT][4], bh[NTG][4];
#pragma unroll
            for (int mt = 0; mt < MT; mt++) ldsm4(ah[mt], aAddrH + mt * (16 * 80) + kb);
#pragma unroll
            for (int bg = 0; bg < NTG; bg++) ldsm4(bh[bg], bAddrH + bg * (16 * 80) + kb);
#pragma unroll
            for (int mt = 0; mt < MT; mt++)
#pragma unroll
                for (int nt = 0; nt < NT; nt++)
                    mma16816(acc[mt][nt], ah[mt], &bh[nt >> 1][(nt & 1) * 2]);
            uint32_t bl[NTG][4];
#pragma unroll
            for (int bg = 0; bg < NTG; bg++) ldsm4(bl[bg], bAddrL + bg * (16 * 80) + kb);
#pragma unroll
            for (int mt = 0; mt < MT; mt++)
#pragma unroll
                for (int nt = 0; nt < NT; nt++)
                    mma16816(acc[mt][nt], ah[mt], &bl[nt >> 1][(nt & 1) * 2]);
            uint32_t al[MT][4];
#pragma unroll
            for (int mt = 0; mt < MT; mt++) ldsm4(al[mt], aAddrL + mt * (16 * 80) + kb);
#pragma unroll
            for (int mt = 0; mt < MT; mt++)
#pragma unroll
                for (int nt = 0; nt < NT; nt++)
                    mma16816(acc[mt][nt], al[mt], &bh[nt >> 1][(nt & 1) * 2]);
        }
    }

    // ---------------- epilogue ----------------
    int gi = lane >> 2, ci = (lane & 3) << 1;
#pragma unroll
    for (int mt = 0; mt < MT; mt++) {
#pragma unroll
        for (int nt = 0; nt < NT; nt++) {
            int nB = nbase + nw + nt * 8 + ci;
            int mA = m0 + mw + mt * 16 + gi;
#pragma unroll
            for (int e = 0; e < 4; e++) {
                int m = mA + ((e >> 1) << 3);
                int nn = nB + (e & 1);
                float v = acc[mt][nt][e];
                if (EPI == 0) {
                    if (nn < 27) C[(size_t)nn * M_TOT + m] = v + p0[nn];
                } else {
                    float sc = p0[nn] * rsqrtf(p3[nn] + 1e-5f);
                    float r = fmaxf(v * sc + (p1[nn] - p2[nn] * sc), 0.f);
                    int b = m >> 12, pix = m & 4095;
                    if (EPI == 1) {
                        C[(((size_t)(b * 256 + nn)) << 12) + pix] = r;
                    } else {
                        int i2 = pix >> 6, j2 = pix & 63;
                        int py = par >> 1, px = par & 1;
                        C[(((size_t)((b * 256 + nn) * 128 + 2 * i2 + py)) << 7) +
                          2 * j2 + px] = r;
                    }
                }
            }
        }
    }
}

// -----------------------------------------------------------------------------
extern "C" void kernel_launch(void* const* d_in, const int* in_sizes, int n_in,
                              void* d_out, int out_size) {
    const float* x     = (const float*)d_in[0];
    const float* w_off = (const float*)d_in[1];
    const float* b_off = (const float*)d_in[2];
    const float* w_mod = (const float*)d_in[3];
    const float* b_mod = (const float*)d_in[4];
    const float* w_reg = (const float*)d_in[5];
    const float* bn1_g = (const float*)d_in[6];
    const float* bn1_b = (const float*)d_in[7];
    const float* bn1_m = (const float*)d_in[8];
    const float* bn1_v = (const float*)d_in[9];
    const float* w_up  = (const float*)d_in[10];
    const float* bn2_g = (const float*)d_in[11];
    const float* bn2_b = (const float*)d_in[12];
    const float* bn2_m = (const float*)d_in[13];
    const float* bn2_v = (const float*)d_in[14];
    float* out = (float*)d_out;

    uint32_t *col, *v, *u;
    float *om, *biasom, *h1;
    __nv_bfloat16 *Wh, *Wl, *Bomh, *Boml, *B2h, *B2l;
    cudaGetSymbolAddress((void**)&col,    g_col);
    cudaGetSymbolAddress((void**)&v,      g_v);
    cudaGetSymbolAddress((void**)&u,      g_u);
    cudaGetSymbolAddress((void**)&om,     g_offmask);
    cudaGetSymbolAddress((void**)&biasom, g_biasom);
    cudaGetSymbolAddress((void**)&h1,     g_h1);
    cudaGetSymbolAddress((void**)&Wh,     g_Wh);
    cudaGetSymbolAddress((void**)&Wl,     g_Wl);
    cudaGetSymbolAddress((void**)&Bomh,   g_Bomh);
    cudaGetSymbolAddress((void**)&Boml,   g_Boml);
    cudaGetSymbolAddress((void**)&B2h,    g_B2h);
    cudaGetSymbolAddress((void**)&B2l,    g_B2l);

    const int smem128 = 2 * (128 * 80) + 2 * (128 * 80);  // 40960
    const int smem32  = 2 * (128 * 80) + 2 * (32 * 80);   // 25600

    // weight packing
    pack_w_kernel<<<4096, 256>>>(w_reg, w_off, b_off, w_mod, b_mod, w_up);

    // stage 0: offset/mask conv (N padded to 32, only 27 written)
    im2col_kernel<<<dim3(128, 2304), 256>>>(x);
    mma_gemm<32, 0><<<dim3(256, 1, 1), 256, smem32>>>(
        col, Bomh, Boml, om, K1, biasom, nullptr, nullptr, nullptr);

    // stage 1: deform sampling + deform GEMM (+BN1+ReLU)
    build_v_kernel<<<dim3(128, 9), 256>>>(x);
    mma_gemm<128, 1><<<dim3(256, 2, 1), 256, smem128>>>(
        v, Wh, Wl, h1, K1, bn1_g, bn1_b, bn1_m, bn1_v);

    // stage 2: conv-transpose as 4 parity GEMMs (+BN2+ReLU, scatter)
    build_u_kernel<<<dim3(128, 4), 256>>>();
    mma_gemm<128, 2><<<dim3(256, 2, 4), 256, smem128>>>(
        u, B2h, B2l, out, K2, bn2_g, bn2_b, bn2_m, bn2_v);
}

// round 5
// speedup vs baseline: 2.3904x; 2.3003x over previous
#include <cuda_runtime.h>
#include <cuda_bf16.h>
#include <math.h>
#include <stdint.h>

#define M_TOT 32768
#define K1 2304
#define K2 1024

// ----------------------------- scratch ---------------------------------------
__device__ uint32_t g_v[(size_t)K1 * M_TOT];        // deform samples, packed hi|lo, (K1, M)
__device__ uint32_t g_h1p[(size_t)8 * 256 * 4096];  // stage-1 out, packed hi|lo, (b,c,pix)
__device__ float    g_offmask[32u * M_TOT];         // offset/mask conv out (27 used rows)
__device__ __nv_bfloat16 g_Wh[256 * K1],  g_Wl[256 * K1];   // w_reg split (N,K)
__device__ __nv_bfloat16 g_Bomh[32 * K1], g_Boml[32 * K1];  // offset+mask weights (pad 32)
__device__ float    g_biasom[32];
__device__ __nv_bfloat16 g_B2h[4 * 256 * K2], g_B2l[4 * 256 * K2]; // convT per-parity (N,K)

// ----------------------------- helpers ---------------------------------------
__device__ __forceinline__ uint32_t smem_u32(const void* p) {
    uint32_t a;
    asm("{ .reg .u64 t; cvta.to.shared.u64 t, %1; cvt.u32.u64 %0, t; }" : "=r"(a) : "l"(p));
    return a;
}
__device__ __forceinline__ void ldsm4(uint32_t* r, uint32_t addr) {
    asm volatile("ldmatrix.sync.aligned.m8n8.x4.shared.b16 {%0,%1,%2,%3}, [%4];"
                 : "=r"(r[0]), "=r"(r[1]), "=r"(r[2]), "=r"(r[3]) : "r"(addr));
}
__device__ __forceinline__ void ldsm4t(uint32_t* r, uint32_t addr) {
    asm volatile("ldmatrix.sync.aligned.m8n8.x4.trans.shared.b16 {%0,%1,%2,%3}, [%4];"
                 : "=r"(r[0]), "=r"(r[1]), "=r"(r[2]), "=r"(r[3]) : "r"(addr));
}
__device__ __forceinline__ void mma16816(float* c, const uint32_t* a, const uint32_t* b) {
    asm volatile(
        "mma.sync.aligned.m16n8k16.row.col.f32.bf16.bf16.f32 "
        "{%0,%1,%2,%3}, {%4,%5,%6,%7}, {%8,%9}, {%0,%1,%2,%3};"
        : "+f"(c[0]), "+f"(c[1]), "+f"(c[2]), "+f"(c[3])
        : "r"(a[0]), "r"(a[1]), "r"(a[2]), "r"(a[3]), "r"(b[0]), "r"(b[1]));
}
__device__ __forceinline__ void cp16(uint32_t dst, const void* src) {
    asm volatile("cp.async.ca.shared.global [%0], [%1], 16;" :: "r"(dst), "l"(src));
}
__device__ __forceinline__ void cp_commit() { asm volatile("cp.async.commit_group;"); }
__device__ __forceinline__ void cp_wait0() { asm volatile("cp.async.wait_group 0;"); }

__device__ __forceinline__ uint32_t packbf(float a) {
    __nv_bfloat16 h = __float2bfloat16(a);
    float hf = __bfloat162float(h);
    __nv_bfloat16 l = __float2bfloat16(a - hf);
    return (uint32_t)__bfloat16_as_ushort(h) | ((uint32_t)__bfloat16_as_ushort(l) << 16);
}
__device__ __forceinline__ void splitbf(float a, __nv_bfloat16& h, __nv_bfloat16& l) {
    h = __float2bfloat16(a);
    l = __float2bfloat16(a - __bfloat162float(h));
}

// ----------------------------- weight packing --------------------------------
__global__ void pack_w_kernel(const float* __restrict__ w_reg, const float* __restrict__ w_off,
                              const float* __restrict__ b_off, const float* __restrict__ w_mod,
                              const float* __restrict__ b_mod, const float* __restrict__ w_up) {
    int i = blockIdx.x * 256 + threadIdx.x;
    if (i < 256 * K1) splitbf(w_reg[i], g_Wh[i], g_Wl[i]);
    if (i < 32 * K1) {
        int n = i / K1;
        float v = 0.f;
        if (n < 18) v = w_off[i];
        else if (n < 27) v = w_mod[i - 18 * K1];
        splitbf(v, g_Bomh[i], g_Boml[i]);
    }
    if (i < 32) g_biasom[i] = (i < 18) ? b_off[i] : ((i < 27) ? b_mod[i - 18] : 0.f);
    if (i < 4 * 256 * K2) {
        int k = i & 1023, n = (i >> 10) & 255, p = i >> 18;
        int c = k >> 2, t = k & 3, ty = t >> 1, tx = t & 1;
        int py = p >> 1, px = p & 1;
        int kh = py ? (ty ? 2 : 0) : (ty ? 3 : 1);
        int kw = px ? (tx ? 2 : 0) : (tx ? 3 : 1);
        splitbf(w_up[(c << 12) + (n << 4) + (kh << 2) + kw], g_B2h[i], g_B2l[i]);
    }
}

// ----------------------------- deform sampling -------------------------------
__global__ void build_v_kernel(const float* __restrict__ x) {
    int m = blockIdx.x * 256 + threadIdx.x;
    int k = blockIdx.y;
    int b = m >> 12, pix = m & 4095, h = pix >> 6, w = pix & 63;
    float oy = g_offmask[(size_t)(2 * k) * M_TOT + m];
    float ox = g_offmask[(size_t)(2 * k + 1) * M_TOT + m];
    float mr = g_offmask[(size_t)(18 + k) * M_TOT + m];
    float mask = 2.f / (1.f + expf(-mr));
    int ky = k / 3, kx = k % 3;
    float py = (float)(h - 1 + ky) + oy;
    float px = (float)(w - 1 + kx) + ox;
    float y0f = floorf(py), x0f = floorf(px);
    float wy1 = py - y0f, wx1 = px - x0f;
    float wy0 = 1.f - wy1, wx0 = 1.f - wx1;
    int y0 = (int)y0f, x0 = (int)x0f, y1 = y0 + 1, x1 = x0 + 1;
    bool vy0 = (y0 >= 0 && y0 < 64), vy1 = (y1 >= 0 && y1 < 64);
    bool vx0 = (x0 >= 0 && x0 < 64), vx1 = (x1 >= 0 && x1 < 64);
    int yc0 = min(max(y0, 0), 63), yc1 = min(max(y1, 0), 63);
    int xc0 = min(max(x0, 0), 63), xc1 = min(max(x1, 0), 63);
    int o00 = (yc0 << 6) + xc0, o01 = (yc0 << 6) + xc1;
    int o10 = (yc1 << 6) + xc0, o11 = (yc1 << 6) + xc1;
    float w00 = wy0 * wx0 * ((vy0 && vx0) ? mask : 0.f);
    float w01 = wy0 * wx1 * ((vy0 && vx1) ? mask : 0.f);
    float w10 = wy1 * wx0 * ((vy1 && vx0) ? mask : 0.f);
    float w11 = wy1 * wx1 * ((vy1 && vx1) ? mask : 0.f);
    const float* xb = x + ((size_t)b << 20);
    for (int c = 0; c < 256; c++) {
        const float* xc = xb + (c << 12);
        float v = w00 * xc[o00] + w01 * xc[o01] + w10 * xc[o10] + w11 * xc[o11];
        g_v[(size_t)(c * 9 + k) * M_TOT + m] = packbf(v);
    }
}

// ----------------------------- unified HMMA GEMM ------------------------------
// C(M=32768, N) = A(K,M)^T x B(N,K)^T, bf16 split (hh + hl + lh), fp32 accum.
// A SMEM: K-major, 32 k-rows x 128 m-cols, 272B row stride, hi/lo planes.
// B SMEM: N-major, NTILE n-rows x 32 k-cols, 80B row stride, hi/lo planes.
// ASRC: 0 = packed u32 (K,M) global; 1 = im2col gather from x (fp32);
//       2 = tap gather from packed h1p.
// EPI:  0 = +bias -> (N,M) fp32; 1 = BN+ReLU -> packed h1p; 2 = BN+ReLU parity scatter.
template <int NTILE, int ASRC, int EPI>
__global__ __launch_bounds__(256) void mma_gemm(
    const void* __restrict__ Asrc, const __nv_bfloat16* __restrict__ Bhg,
    const __nv_bfloat16* __restrict__ Blg, void* __restrict__ Cout, int K,
    const float* __restrict__ p0, const float* __restrict__ p1,
    const float* __restrict__ p2, const float* __restrict__ p3) {
    constexpr int WN = (NTILE >= 128) ? 4 : 2;
    constexpr int WM = 8 / WN;
    constexpr int WARP_M = 128 / WM;
    constexpr int WARP_N = NTILE / WN;
    constexpr int MT = WARP_M / 16;
    constexpr int NTG = WARP_N / 16;
    constexpr int NT = NTG * 2;
    constexpr int A_PLANE = 32 * 272;            // 8704
    constexpr int B_PLANE = NTILE * 80;
    constexpr int B_OFF = 2 * A_PLANE;           // 17408
    constexpr int STAGE = B_OFF + 2 * B_PLANE;
    constexpr int BCH = 2 * NTILE * 4;           // cp.async 16B chunks per stage
    constexpr int BJ = (BCH + 255) / 256;

    extern __shared__ char sb[];
    uint32_t sbase = smem_u32(sb);

    int t = threadIdx.x, warp = t >> 5, lane = t & 31;
    int ntile_id, par;
    if (ASRC == 2) { par = blockIdx.x >> 1; ntile_id = blockIdx.x & 1; }
    else { par = 0; ntile_id = blockIdx.x; }
    int nbase = ntile_id * NTILE;
    int m0 = blockIdx.y * 128;
    int py = par >> 1, px = par & 1;

    const __nv_bfloat16* Bh = Bhg + ((size_t)par * 256 + nbase) * K;
    const __nv_bfloat16* Bl = Blg + ((size_t)par * 256 + nbase) * K;

    int mw = (warp / WN) * WARP_M;
    int nw = (warp % WN) * WARP_N;

    // ldmatrix lane addressing
    int g = lane >> 3;
    int a_k = (lane & 7) + ((g >> 1) << 3);        // stored k-row (0..15)
    int a_moff = (g & 1) << 3;                     // m within 16-tile
    uint32_t aBase = (uint32_t)(a_k * 272 + (mw + a_moff) * 2);
    int b_row = (lane & 7) | ((lane >> 4) << 3);
    int b_kh = ((lane >> 3) & 1) << 3;
    uint32_t bBase = (uint32_t)(B_OFF + (nw + b_row) * 80 + b_kh * 2);

    float acc[MT][NT][4];
#pragma unroll
    for (int i = 0; i < MT; i++)
#pragma unroll
        for (int j = 0; j < NT; j++)
#pragma unroll
            for (int e = 0; e < 4; e++) acc[i][j][e] = 0.f;

    uint32_t areg[16];
    float freg[16];
    int nch = K >> 5;

    // ---- A loader: global -> regs for chunk cc
    auto loadA = [&](int cc) {
        int k0 = cc << 5;
#pragma unroll
        for (int i = 0; i < 16; i++) {
            int e = t + i * 256;
            int k = e >> 7, m = e & 127;
            if (ASRC == 0) {
                const uint32_t* Ag = (const uint32_t*)Asrc;
                areg[i] = Ag[(size_t)(k0 + k) * M_TOT + m0 + m];
            } else {
                int gm = m0 + m;
                int b = gm >> 12, pix = gm & 4095, ii = pix >> 6, jj = pix & 63;
                int kk = k0 + k;
                if (ASRC == 1) {
                    int c = kk / 9, tt = kk - 9 * c, ty = tt / 3, tx = tt - 3 * ty;
                    int y = ii + ty - 1, xx = jj + tx - 1;
                    bool ok = ((unsigned)y < 64u) && ((unsigned)xx < 64u);
                    const float* xg = (const float*)Asrc;
                    freg[i] = ok ? xg[(((size_t)(b * 256 + c)) << 12) + (y << 6) + xx] : 0.f;
                } else {
                    int c = kk >> 2, tt = kk & 3, ty = tt >> 1, tx = tt & 1;
                    int r = ii + py - ty, ccx = jj + px - tx;
                    bool ok = ((unsigned)r < 64u) && ((unsigned)ccx < 64u);
                    const uint32_t* hp = (const uint32_t*)Asrc;
                    areg[i] = ok ? hp[(((size_t)(b * 256 + c)) << 12) + (r << 6) + ccx] : 0u;
                }
            }
        }
    };
    // ---- A store: regs -> SMEM stage
    auto storeA = [&](int s) {
        char* sA = sb + s * STAGE;
#pragma unroll
        for (int i = 0; i < 16; i++) {
            int e = t + i * 256;
            int k = e >> 7, m = e & 127;
            int off = k * 272 + m * 2;
            uint32_t w;
            if (ASRC == 1) {
                __nv_bfloat16 h, l;
                splitbf(freg[i], h, l);
                w = (uint32_t)__bfloat16_as_ushort(h) |
                    ((uint32_t)__bfloat16_as_ushort(l) << 16);
            } else {
                w = areg[i];
            }
            *(uint16_t*)(sA + off) = (uint16_t)w;
            *(uint16_t*)(sA + A_PLANE + off) = (uint16_t)(w >> 16);
        }
    };
    // ---- B fill via cp.async
    auto fillB = [&](int cc, int s) {
        int k0 = cc << 5;
        uint32_t base = sbase + s * STAGE + B_OFF;
#pragma unroll
        for (int j = 0; j < BJ; j++) {
            int idx = t + j * 256;
            if (idx < BCH) {
                int plane = idx / (NTILE * 4);
                int rem = idx - plane * (NTILE * 4);
                int r = rem >> 2, q = rem & 3;
                const __nv_bfloat16* src =
                    (plane ? Bl : Bh) + (size_t)r * K + k0 + q * 8;
                cp16(base + plane * B_PLANE + r * 80 + q * 16, src);
            }
        }
    };
    // ---- MMA on stage s
    auto domma = [&](int s) {
        uint32_t sA0 = sbase + s * STAGE;
#pragma unroll
        for (int ks = 0; ks < 2; ks++) {
            uint32_t aoff = sA0 + aBase + ks * 4352;
            uint32_t boff = sA0 + bBase + ks * 32;
            uint32_t ah[MT][4], bh[NTG][4];
#pragma unroll
            for (int mt = 0; mt < MT; mt++) ldsm4t(ah[mt], aoff + mt * 32);
#pragma unroll
            for (int bg = 0; bg < NTG; bg++) ldsm4(bh[bg], boff + bg * 1280);
#pragma unroll
            for (int mt = 0; mt < MT; mt++)
#pragma unroll
                for (int nt = 0; nt < NT; nt++)
                    mma16816(acc[mt][nt], ah[mt], &bh[nt >> 1][(nt & 1) * 2]);
            uint32_t bl[NTG][4];
#pragma unroll
            for (int bg = 0; bg < NTG; bg++) ldsm4(bl[bg], boff + B_PLANE + bg * 1280);
#pragma unroll
            for (int mt = 0; mt < MT; mt++)
#pragma unroll
                for (int nt = 0; nt < NT; nt++)
                    mma16816(acc[mt][nt], ah[mt], &bl[nt >> 1][(nt & 1) * 2]);
            uint32_t al[MT][4];
#pragma unroll
            for (int mt = 0; mt < MT; mt++) ldsm4t(al[mt], aoff + A_PLANE + mt * 32);
#pragma unroll
            for (int mt = 0; mt < MT; mt++)
#pragma unroll
                for (int nt = 0; nt < NT; nt++)
                    mma16816(acc[mt][nt], al[mt], &bh[nt >> 1][(nt & 1) * 2]);
        }
    };

    // ---- prologue: fill stage 0
    fillB(0, 0);
    cp_commit();
    loadA(0);
    storeA(0);
    cp_wait0();
    __syncthreads();

    for (int c = 0; c < nch; c++) {
        int s = c & 1;
        if (c + 1 < nch) {
            loadA(c + 1);       // LDG issued; regs consumed after MMA
            fillB(c + 1, s ^ 1);
            cp_commit();
        }
        domma(s);
        __syncthreads();
        if (c + 1 < nch) storeA(s ^ 1);
        cp_wait0();
        __syncthreads();
    }

    // ---------------- epilogue ----------------
    int gi = lane >> 2, ci = (lane & 3) << 1;
#pragma unroll
    for (int mt = 0; mt < MT; mt++) {
#pragma unroll
        for (int nt = 0; nt < NT; nt++) {
            int nB = nbase + nw + nt * 8 + ci;
            int mA = m0 + mw + mt * 16 + gi;
#pragma unroll
            for (int e = 0; e < 4; e++) {
                int m = mA + ((e >> 1) << 3);
                int nn = nB + (e & 1);
                float v = acc[mt][nt][e];
                if (EPI == 0) {
                    if (nn < 27)
                        ((float*)Cout)[(size_t)nn * M_TOT + m] = v + p0[nn];
                } else {
                    float sc = p0[nn] * rsqrtf(p3[nn] + 1e-5f);
                    float r = fmaxf(v * sc + (p1[nn] - p2[nn] * sc), 0.f);
                    int b = m >> 12, pix = m & 4095;
                    if (EPI == 1) {
                        ((uint32_t*)Cout)[(((size_t)(b * 256 + nn)) << 12) + pix] =
                            packbf(r);
                    } else {
                        int i2 = pix >> 6, j2 = pix & 63;
                        ((float*)Cout)[(((size_t)((b * 256 + nn) * 128 + 2 * i2 + py))
                                        << 7) + 2 * j2 + px] = r;
                    }
                }
            }
        }
    }
}

// -----------------------------------------------------------------------------
extern "C" void kernel_launch(void* const* d_in, const int* in_sizes, int n_in,
                              void* d_out, int out_size) {
    const float* x     = (const float*)d_in[0];
    const float* w_off = (const float*)d_in[1];
    const float* b_off = (const float*)d_in[2];
    const float* w_mod = (const float*)d_in[3];
    const float* b_mod = (const float*)d_in[4];
    const float* w_reg = (const float*)d_in[5];
    const float* bn1_g = (const float*)d_in[6];
    const float* bn1_b = (const float*)d_in[7];
    const float* bn1_m = (const float*)d_in[8];
    const float* bn1_v = (const float*)d_in[9];
    const float* w_up  = (const float*)d_in[10];
    const float* bn2_g = (const float*)d_in[11];
    const float* bn2_b = (const float*)d_in[12];
    const float* bn2_m = (const float*)d_in[13];
    const float* bn2_v = (const float*)d_in[14];
    float* out = (float*)d_out;

    uint32_t *v, *h1p;
    float *om, *biasom;
    __nv_bfloat16 *Wh, *Wl, *Bomh, *Boml, *B2h, *B2l;
    cudaGetSymbolAddress((void**)&v,      g_v);
    cudaGetSymbolAddress((void**)&h1p,    g_h1p);
    cudaGetSymbolAddress((void**)&om,     g_offmask);
    cudaGetSymbolAddress((void**)&biasom, g_biasom);
    cudaGetSymbolAddress((void**)&Wh,     g_Wh);
    cudaGetSymbolAddress((void**)&Wl,     g_Wl);
    cudaGetSymbolAddress((void**)&Bomh,   g_Bomh);
    cudaGetSymbolAddress((void**)&Boml,   g_Boml);
    cudaGetSymbolAddress((void**)&B2h,    g_B2h);
    cudaGetSymbolAddress((void**)&B2l,    g_B2l);

    const int STAGE128 = 17408 + 2 * (128 * 80);  // 37888
    const int STAGE32  = 17408 + 2 * (32 * 80);   // 22528
    const int smem128 = 2 * STAGE128;             // 75776
    const int smem32  = 2 * STAGE32;              // 45056
    cudaFuncSetAttribute(mma_gemm<32, 1, 0>,
                         cudaFuncAttributeMaxDynamicSharedMemorySize, smem32);
    cudaFuncSetAttribute(mma_gemm<128, 0, 1>,
                         cudaFuncAttributeMaxDynamicSharedMemorySize, smem128);
    cudaFuncSetAttribute(mma_gemm<128, 2, 2>,
                         cudaFuncAttributeMaxDynamicSharedMemorySize, smem128);

    // weight packing
    pack_w_kernel<<<4096, 256>>>(w_reg, w_off, b_off, w_mod, b_mod, w_up);

    // stage 0: offset/mask conv (im2col fused into GEMM A-fill)
    mma_gemm<32, 1, 0><<<dim3(1, 256), 256, smem32>>>(
        x, Bomh, Boml, om, K1, biasom, nullptr, nullptr, nullptr);

    // stage 1: deform sampling + deform GEMM (+BN1+ReLU -> packed h1p)
    build_v_kernel<<<dim3(128, 9), 256>>>(x);
    mma_gemm<128, 0, 1><<<dim3(2, 256), 256, smem128>>>(
        v, Wh, Wl, h1p, K1, bn1_g, bn1_b, bn1_m, bn1_v);

    // stage 2: conv-transpose; A gathered from h1p per parity (+BN2+ReLU scatter)
    mma_gemm<128, 2, 2><<<dim3(8, 256), 256, smem128>>>(
        h1p, B2h, B2l, out, K2, bn2_g, bn2_b, bn2_m, bn2_v);
}

// round 6
// speedup vs baseline: 2.8030x; 1.1726x over previous
#include <cuda_runtime.h>
#include <cuda_bf16.h>
#include <math.h>
#include <stdint.h>

#define M_TOT 32768
#define K1 2304
#define K2 1024

// ----------------------------- scratch ---------------------------------------
__device__ __nv_bfloat16 g_vh[(size_t)K1 * M_TOT];  // deform samples hi plane, (K1, M)
__device__ __nv_bfloat16 g_vl[(size_t)K1 * M_TOT];  // deform samples lo plane, (K1, M)
__device__ uint32_t g_h1p[(size_t)8 * 256 * 4096];  // stage-1 out, packed hi|lo, (b,c,pix)
__device__ float    g_offmask[32u * M_TOT];         // offset/mask conv out (27 used rows)
__device__ __nv_bfloat16 g_Wh[256 * K1],  g_Wl[256 * K1];   // w_reg split (N,K)
__device__ __nv_bfloat16 g_Bomh[32 * K1], g_Boml[32 * K1];  // offset+mask weights (pad 32)
__device__ float    g_biasom[32];
__device__ __nv_bfloat16 g_B2h[4 * 256 * K2], g_B2l[4 * 256 * K2]; // convT per-parity (N,K)

// ----------------------------- helpers ---------------------------------------
__device__ __forceinline__ uint32_t smem_u32(const void* p) {
    uint32_t a;
    asm("{ .reg .u64 t; cvta.to.shared.u64 t, %1; cvt.u32.u64 %0, t; }" : "=r"(a) : "l"(p));
    return a;
}
__device__ __forceinline__ void ldsm4(uint32_t* r, uint32_t addr) {
    asm volatile("ldmatrix.sync.aligned.m8n8.x4.shared.b16 {%0,%1,%2,%3}, [%4];"
                 : "=r"(r[0]), "=r"(r[1]), "=r"(r[2]), "=r"(r[3]) : "r"(addr));
}
__device__ __forceinline__ void ldsm4t(uint32_t* r, uint32_t addr) {
    asm volatile("ldmatrix.sync.aligned.m8n8.x4.trans.shared.b16 {%0,%1,%2,%3}, [%4];"
                 : "=r"(r[0]), "=r"(r[1]), "=r"(r[2]), "=r"(r[3]) : "r"(addr));
}
__device__ __forceinline__ void mma16816(float* c, const uint32_t* a, const uint32_t* b) {
    asm volatile(
        "mma.sync.aligned.m16n8k16.row.col.f32.bf16.bf16.f32 "
        "{%0,%1,%2,%3}, {%4,%5,%6,%7}, {%8,%9}, {%0,%1,%2,%3};"
        : "+f"(c[0]), "+f"(c[1]), "+f"(c[2]), "+f"(c[3])
        : "r"(a[0]), "r"(a[1]), "r"(a[2]), "r"(a[3]), "r"(b[0]), "r"(b[1]));
}
__device__ __forceinline__ void cp16(uint32_t dst, const void* src) {
    asm volatile("cp.async.ca.shared.global [%0], [%1], 16;" :: "r"(dst), "l"(src));
}
__device__ __forceinline__ void cp_commit() { asm volatile("cp.async.commit_group;"); }
__device__ __forceinline__ void cp_wait0() { asm volatile("cp.async.wait_group 0;"); }

__device__ __forceinline__ uint32_t packbf(float a) {
    __nv_bfloat16 h = __float2bfloat16(a);
    float hf = __bfloat162float(h);
    __nv_bfloat16 l = __float2bfloat16(a - hf);
    return (uint32_t)__bfloat16_as_ushort(h) | ((uint32_t)__bfloat16_as_ushort(l) << 16);
}
__device__ __forceinline__ void splitbf(float a, __nv_bfloat16& h, __nv_bfloat16& l) {
    h = __float2bfloat16(a);
    l = __float2bfloat16(a - __bfloat162float(h));
}

// ----------------------------- weight packing --------------------------------
__global__ void pack_w_kernel(const float* __restrict__ w_reg, const float* __restrict__ w_off,
                              const float* __restrict__ b_off, const float* __restrict__ w_mod,
                              const float* __restrict__ b_mod, const float* __restrict__ w_up) {
    int i = blockIdx.x * 256 + threadIdx.x;
    if (i < 256 * K1) splitbf(w_reg[i], g_Wh[i], g_Wl[i]);
    if (i < 32 * K1) {
        int n = i / K1;
        float v = 0.f;
        if (n < 18) v = w_off[i];
        else if (n < 27) v = w_mod[i - 18 * K1];
        splitbf(v, g_Bomh[i], g_Boml[i]);
    }
    if (i < 32) g_biasom[i] = (i < 18) ? b_off[i] : ((i < 27) ? b_mod[i - 18] : 0.f);
    if (i < 4 * 256 * K2) {
        int k = i & 1023, n = (i >> 10) & 255, p = i >> 18;
        int c = k >> 2, t = k & 3, ty = t >> 1, tx = t & 1;
        int py = p >> 1, px = p & 1;
        int kh = py ? (ty ? 2 : 0) : (ty ? 3 : 1);
        int kw = px ? (tx ? 2 : 0) : (tx ? 3 : 1);
        splitbf(w_up[(c << 12) + (n << 4) + (kh << 2) + kw], g_B2h[i], g_B2l[i]);
    }
}

// ----------------------------- deform sampling -------------------------------
__global__ void build_v_kernel(const float* __restrict__ x) {
    int m = blockIdx.x * 256 + threadIdx.x;
    int k = blockIdx.y;
    int b = m >> 12, pix = m & 4095, h = pix >> 6, w = pix & 63;
    float oy = g_offmask[(size_t)(2 * k) * M_TOT + m];
    float ox = g_offmask[(size_t)(2 * k + 1) * M_TOT + m];
    float mr = g_offmask[(size_t)(18 + k) * M_TOT + m];
    float mask = 2.f / (1.f + expf(-mr));
    int ky = k / 3, kx = k % 3;
    float py = (float)(h - 1 + ky) + oy;
    float px = (float)(w - 1 + kx) + ox;
    float y0f = floorf(py), x0f = floorf(px);
    float wy1 = py - y0f, wx1 = px - x0f;
    float wy0 = 1.f - wy1, wx0 = 1.f - wx1;
    int y0 = (int)y0f, x0 = (int)x0f, y1 = y0 + 1, x1 = x0 + 1;
    bool vy0 = (y0 >= 0 && y0 < 64), vy1 = (y1 >= 0 && y1 < 64);
    bool vx0 = (x0 >= 0 && x0 < 64), vx1 = (x1 >= 0 && x1 < 64);
    int yc0 = min(max(y0, 0), 63), yc1 = min(max(y1, 0), 63);
    int xc0 = min(max(x0, 0), 63), xc1 = min(max(x1, 0), 63);
    int o00 = (yc0 << 6) + xc0, o01 = (yc0 << 6) + xc1;
    int o10 = (yc1 << 6) + xc0, o11 = (yc1 << 6) + xc1;
    float w00 = wy0 * wx0 * ((vy0 && vx0) ? mask : 0.f);
    float w01 = wy0 * wx1 * ((vy0 && vx1) ? mask : 0.f);
    float w10 = wy1 * wx0 * ((vy1 && vx0) ? mask : 0.f);
    float w11 = wy1 * wx1 * ((vy1 && vx1) ? mask : 0.f);
    const float* xb = x + ((size_t)b << 20);
    for (int c = 0; c < 256; c++) {
        const float* xc = xb + (c << 12);
        float v = w00 * xc[o00] + w01 * xc[o01] + w10 * xc[o10] + w11 * xc[o11];
        __nv_bfloat16 h16, l16;
        splitbf(v, h16, l16);
        size_t idx = (size_t)(c * 9 + k) * M_TOT + m;
        g_vh[idx] = h16;
        g_vl[idx] = l16;
    }
}

// ----------------------------- unified HMMA GEMM ------------------------------
// C(M=32768, N) = A(K,M)^T x B(N,K)^T, bf16 split (hh + hl + lh), fp32 accum.
// A SMEM: K-major, 32 k-rows x 128 m-cols, 272B row stride, hi/lo planes.
// B SMEM: N-major, NTILE n-rows x 32 k-cols, 80B row stride, hi/lo planes.
// ASRC: 0 = plane arrays g_vh/g_vl (cp.async); 1 = im2col gather from x (fp32);
//       2 = tap gather from packed h1p.
// EPI:  0 = +bias -> (N,M) fp32; 1 = BN+ReLU -> packed h1p; 2 = BN+ReLU parity scatter.
template <int NTILE, int ASRC, int EPI>
__global__ __launch_bounds__(256, 2) void mma_gemm(
    const void* __restrict__ Asrc, const void* __restrict__ Asrc2,
    const __nv_bfloat16* __restrict__ Bhg, const __nv_bfloat16* __restrict__ Blg,
    void* __restrict__ Cout, int K,
    const float* __restrict__ p0, const float* __restrict__ p1,
    const float* __restrict__ p2, const float* __restrict__ p3) {
    constexpr int WN = (NTILE >= 128) ? 4 : 2;
    constexpr int WM = 8 / WN;
    constexpr int WARP_M = 128 / WM;
    constexpr int WARP_N = NTILE / WN;
    constexpr int MT = WARP_M / 16;
    constexpr int NTG = WARP_N / 16;
    constexpr int NT = NTG * 2;
    constexpr int A_PLANE = 32 * 272;            // 8704
    constexpr int B_PLANE = NTILE * 80;
    constexpr int B_OFF = 2 * A_PLANE;           // 17408
    constexpr int STAGE = B_OFF + 2 * B_PLANE;
    constexpr int BCH = 2 * NTILE * 4;           // cp.async 16B chunks per stage (B)
    constexpr int BJ = (BCH + 255) / 256;

    extern __shared__ char sb[];
    uint32_t sbase = smem_u32(sb);

    int t = threadIdx.x, warp = t >> 5, lane = t & 31;
    int ntile_id, par;
    if (ASRC == 2) { par = blockIdx.x >> 1; ntile_id = blockIdx.x & 1; }
    else { par = 0; ntile_id = blockIdx.x; }
    int nbase = ntile_id * NTILE;
    int m0 = blockIdx.y * 128;
    int py = par >> 1, px = par & 1;

    const __nv_bfloat16* Bh = Bhg + ((size_t)par * 256 + nbase) * K;
    const __nv_bfloat16* Bl = Blg + ((size_t)par * 256 + nbase) * K;

    int mw = (warp / WN) * WARP_M;
    int nw = (warp % WN) * WARP_N;

    // ldmatrix lane addressing
    int g = lane >> 3;
    int a_k = (lane & 7) + ((g >> 1) << 3);
    int a_moff = (g & 1) << 3;
    uint32_t aBase = (uint32_t)(a_k * 272 + (mw + a_moff) * 2);
    int b_row = (lane & 7) | ((lane >> 4) << 3);
    int b_kh = ((lane >> 3) & 1) << 3;
    uint32_t bBase = (uint32_t)(B_OFF + (nw + b_row) * 80 + b_kh * 2);

    float acc[MT][NT][4];
#pragma unroll
    for (int i = 0; i < MT; i++)
#pragma unroll
        for (int j = 0; j < NT; j++)
#pragma unroll
            for (int e = 0; e < 4; e++) acc[i][j][e] = 0.f;

    int nch = K >> 5;

    // ---- A fill into stage s for chunk cc
    auto fillA = [&](int cc, int s) {
        int k0 = cc << 5;
        if (ASRC == 0) {
            const __nv_bfloat16* vh = (const __nv_bfloat16*)Asrc;
            const __nv_bfloat16* vl = (const __nv_bfloat16*)Asrc2;
            uint32_t base = sbase + s * STAGE;
#pragma unroll
            for (int j = 0; j < 4; j++) {
                int idx = t + j * 256;          // 1024 chunks
                int p = idx >> 9, rem = idx & 511;
                int k = rem >> 4, q = rem & 15;
                const __nv_bfloat16* src =
                    (p ? vl : vh) + (size_t)(k0 + k) * M_TOT + m0 + q * 8;
                cp16(base + p * A_PLANE + k * 272 + q * 16, src);
            }
        } else {
            char* sA = sb + s * STAGE;
#pragma unroll
            for (int j = 0; j < 4; j++) {
                int gi = t + j * 256;           // 1024 groups of 4 m
                int k = gi >> 5, m4 = (gi & 31) << 2;
                int kk = k0 + k;
                uint32_t h01, h23, l01, l23;
                if (ASRC == 1) {
                    int c = kk / 9, tt = kk - 9 * c, ty = tt / 3, tx = tt - 3 * ty;
                    const float* xg = (const float*)Asrc;
                    uint32_t hi[4], lo[4];
#pragma unroll
                    for (int e = 0; e < 4; e++) {
                        int gm = m0 + m4 + e;
                        int b = gm >> 12, pix = gm & 4095, ii = pix >> 6, jj = pix & 63;
                        int y = ii + ty - 1, xx = jj + tx - 1;
                        bool ok = ((unsigned)y < 64u) && ((unsigned)xx < 64u);
                        float f = ok ? xg[(((size_t)(b * 256 + c)) << 12) + (y << 6) + xx] : 0.f;
                        __nv_bfloat16 h16, l16;
                        splitbf(f, h16, l16);
                        hi[e] = __bfloat16_as_ushort(h16);
                        lo[e] = __bfloat16_as_ushort(l16);
                    }
                    h01 = hi[0] | (hi[1] << 16); h23 = hi[2] | (hi[3] << 16);
                    l01 = lo[0] | (lo[1] << 16); l23 = lo[2] | (lo[3] << 16);
                } else {
                    int c = kk >> 2, tt = kk & 3, ty = tt >> 1, tx = tt & 1;
                    const uint32_t* hp = (const uint32_t*)Asrc;
                    uint32_t w[4];
#pragma unroll
                    for (int e = 0; e < 4; e++) {
                        int gm = m0 + m4 + e;
                        int b = gm >> 12, pix = gm & 4095, ii = pix >> 6, jj = pix & 63;
                        int r = ii + py - ty, cx = jj + px - tx;
                        bool ok = ((unsigned)r < 64u) && ((unsigned)cx < 64u);
                        w[e] = ok ? hp[(((size_t)(b * 256 + c)) << 12) + (r << 6) + cx] : 0u;
                    }
                    h01 = (w[0] & 0xFFFFu) | (w[1] << 16);
                    h23 = (w[2] & 0xFFFFu) | (w[3] << 16);
                    l01 = (w[0] >> 16) | (w[1] & 0xFFFF0000u);
                    l23 = (w[2] >> 16) | (w[3] & 0xFFFF0000u);
                }
                int off = k * 272 + m4 * 2;
                *(uint2*)(sA + off) = make_uint2(h01, h23);
                *(uint2*)(sA + A_PLANE + off) = make_uint2(l01, l23);
            }
        }
    };
    // ---- B fill via cp.async
    auto fillB = [&](int cc, int s) {
        int k0 = cc << 5;
        uint32_t base = sbase + s * STAGE + B_OFF;
#pragma unroll
        for (int j = 0; j < BJ; j++) {
            int idx = t + j * 256;
            if (idx < BCH) {
                int plane = idx / (NTILE * 4);
                int rem = idx - plane * (NTILE * 4);
                int r = rem >> 2, q = rem & 3;
                const __nv_bfloat16* src =
                    (plane ? Bl : Bh) + (size_t)r * K + k0 + q * 8;
                cp16(base + plane * B_PLANE + r * 80 + q * 16, src);
            }
        }
    };
    // ---- MMA on stage s
    auto domma = [&](int s) {
        uint32_t sA0 = sbase + s * STAGE;
#pragma unroll
        for (int ks = 0; ks < 2; ks++) {
            uint32_t aoff = sA0 + aBase + ks * 4352;
            uint32_t boff = sA0 + bBase + ks * 32;
            uint32_t ah[MT][4], bh[NTG][4];
#pragma unroll
            for (int mt = 0; mt < MT; mt++) ldsm4t(ah[mt], aoff + mt * 32);
#pragma unroll
            for (int bg = 0; bg < NTG; bg++) ldsm4(bh[bg], boff + bg * 1280);
#pragma unroll
            for (int mt = 0; mt < MT; mt++)
#pragma unroll
                for (int nt = 0; nt < NT; nt++)
                    mma16816(acc[mt][nt], ah[mt], &bh[nt >> 1][(nt & 1) * 2]);
            uint32_t bl[NTG][4];
#pragma unroll
            for (int bg = 0; bg < NTG; bg++) ldsm4(bl[bg], boff + B_PLANE + bg * 1280);
#pragma unroll
            for (int mt = 0; mt < MT; mt++)
#pragma unroll
                for (int nt = 0; nt < NT; nt++)
                    mma16816(acc[mt][nt], ah[mt], &bl[nt >> 1][(nt & 1) * 2]);
            uint32_t al[MT][4];
#pragma unroll
            for (int mt = 0; mt < MT; mt++) ldsm4t(al[mt], aoff + A_PLANE + mt * 32);
#pragma unroll
            for (int mt = 0; mt < MT; mt++)
#pragma unroll
                for (int nt = 0; nt < NT; nt++)
                    mma16816(acc[mt][nt], al[mt], &bh[nt >> 1][(nt & 1) * 2]);
        }
    };

    // ---- prologue: fill stage 0
    fillA(0, 0);
    fillB(0, 0);
    cp_commit();
    cp_wait0();
    __syncthreads();

    for (int c = 0; c < nch; c++) {
        int s = c & 1;
        if (c + 1 < nch) {
            fillA(c + 1, s ^ 1);
            fillB(c + 1, s ^ 1);
            cp_commit();
        }
        domma(s);
        cp_wait0();
        __syncthreads();
    }

    // ---------------- epilogue ----------------
    int gi = lane >> 2, ci = (lane & 3) << 1;
#pragma unroll
    for (int mt = 0; mt < MT; mt++) {
#pragma unroll
        for (int nt = 0; nt < NT; nt++) {
            int nB = nbase + nw + nt * 8 + ci;
            int mA = m0 + mw + mt * 16 + gi;
#pragma unroll
            for (int e = 0; e < 4; e++) {
                int m = mA + ((e >> 1) << 3);
                int nn = nB + (e & 1);
                float v = acc[mt][nt][e];
                if (EPI == 0) {
                    if (nn < 27)
                        ((float*)Cout)[(size_t)nn * M_TOT + m] = v + p0[nn];
                } else {
                    float sc = p0[nn] * rsqrtf(p3[nn] + 1e-5f);
                    float r = fmaxf(v * sc + (p1[nn] - p2[nn] * sc), 0.f);
                    int b = m >> 12, pix = m & 4095;
                    if (EPI == 1) {
                        ((uint32_t*)Cout)[(((size_t)(b * 256 + nn)) << 12) + pix] =
                            packbf(r);
                    } else {
                        int i2 = pix >> 6, j2 = pix & 63;
                        ((float*)Cout)[(((size_t)((b * 256 + nn) * 128 + 2 * i2 + py))
                                        << 7) + 2 * j2 + px] = r;
                    }
                }
            }
        }
    }
}

// -----------------------------------------------------------------------------
extern "C" void kernel_launch(void* const* d_in, const int* in_sizes, int n_in,
                              void* d_out, int out_size) {
    const float* x     = (const float*)d_in[0];
    const float* w_off = (const float*)d_in[1];
    const float* b_off = (const float*)d_in[2];
    const float* w_mod = (const float*)d_in[3];
    const float* b_mod = (const float*)d_in[4];
    const float* w_reg = (const float*)d_in[5];
    const float* bn1_g = (const float*)d_in[6];
    const float* bn1_b = (const float*)d_in[7];
    const float* bn1_m = (const float*)d_in[8];
    const float* bn1_v = (const float*)d_in[9];
    const float* w_up  = (const float*)d_in[10];
    const float* bn2_g = (const float*)d_in[11];
    const float* bn2_b = (const float*)d_in[12];
    const float* bn2_m = (const float*)d_in[13];
    const float* bn2_v = (const float*)d_in[14];
    float* out = (float*)d_out;

    __nv_bfloat16 *vh, *vl, *Wh, *Wl, *Bomh, *Boml, *B2h, *B2l;
    uint32_t* h1p;
    float *om, *biasom;
    cudaGetSymbolAddress((void**)&vh,     g_vh);
    cudaGetSymbolAddress((void**)&vl,     g_vl);
    cudaGetSymbolAddress((void**)&h1p,    g_h1p);
    cudaGetSymbolAddress((void**)&om,     g_offmask);
    cudaGetSymbolAddress((void**)&biasom, g_biasom);
    cudaGetSymbolAddress((void**)&Wh,     g_Wh);
    cudaGetSymbolAddress((void**)&Wl,     g_Wl);
    cudaGetSymbolAddress((void**)&Bomh,   g_Bomh);
    cudaGetSymbolAddress((void**)&Boml,   g_Boml);
    cudaGetSymbolAddress((void**)&B2h,    g_B2h);
    cudaGetSymbolAddress((void**)&B2l,    g_B2l);

    const int STAGE128 = 17408 + 2 * (128 * 80);  // 37888
    const int STAGE32  = 17408 + 2 * (32 * 80);   // 22528
    const int smem128 = 2 * STAGE128;             // 75776
    const int smem32  = 2 * STAGE32;              // 45056
    cudaFuncSetAttribute(mma_gemm<32, 1, 0>,
                         cudaFuncAttributeMaxDynamicSharedMemorySize, smem32);
    cudaFuncSetAttribute(mma_gemm<128, 0, 1>,
                         cudaFuncAttributeMaxDynamicSharedMemorySize, smem128);
    cudaFuncSetAttribute(mma_gemm<128, 2, 2>,
                         cudaFuncAttributeMaxDynamicSharedMemorySize, smem128);

    // weight packing
    pack_w_kernel<<<4096, 256>>>(w_reg, w_off, b_off, w_mod, b_mod, w_up);

    // stage 0: offset/mask conv (im2col fused into GEMM A-fill)
    mma_gemm<32, 1, 0><<<dim3(1, 256), 256, smem32>>>(
        x, nullptr, Bomh, Boml, om, K1, biasom, nullptr, nullptr, nullptr);

    // stage 1: deform sampling + deform GEMM (+BN1+ReLU -> packed h1p)
    build_v_kernel<<<dim3(128, 9), 256>>>(x);
    mma_gemm<128, 0, 1><<<dim3(2, 256), 256, smem128>>>(
        vh, vl, Wh, Wl, h1p, K1, bn1_g, bn1_b, bn1_m, bn1_v);

    // stage 2: conv-transpose; A gathered from h1p per parity (+BN2+ReLU scatter)
    mma_gemm<128, 2, 2><<<dim3(8, 256), 256, smem128>>>(
        h1p, nullptr, B2h, B2l, out, K2, bn2_g, bn2_b, bn2_m, bn2_v);
}

// round 7
// speedup vs baseline: 3.6097x; 1.2878x over previous
#include <cuda_runtime.h>
#include <cuda_fp16.h>
#include <math.h>
#include <stdint.h>

#define M_TOT 32768
#define K1 2304
#define K2 1024

// ----------------------------- scratch ---------------------------------------
__device__ __half g_vh[(size_t)K1 * M_TOT];         // deform samples hi plane, (K1, M)
__device__ __half g_vl[(size_t)K1 * M_TOT];         // deform samples lo plane, (K1, M)
__device__ uint32_t g_h1p[(size_t)8 * 256 * 4096];  // stage-1 out, packed fp16 hi|lo
__device__ float    g_offmask[32u * M_TOT];         // offset/mask conv out (27 used rows)
__device__ __half g_Wh[256 * K1];                   // w_reg fp16 (N,K)
__device__ __half g_Bomh[32 * K1];                  // offset+mask weights (pad 32)
__device__ float  g_biasom[32];
__device__ __half g_B2h[4 * 256 * K2];              // convT per-parity (N,K)

// ----------------------------- helpers ---------------------------------------
__device__ __forceinline__ uint32_t smem_u32(const void* p) {
    uint32_t a;
    asm("{ .reg .u64 t; cvta.to.shared.u64 t, %1; cvt.u32.u64 %0, t; }" : "=r"(a) : "l"(p));
    return a;
}
__device__ __forceinline__ void ldsm4(uint32_t* r, uint32_t addr) {
    asm volatile("ldmatrix.sync.aligned.m8n8.x4.shared.b16 {%0,%1,%2,%3}, [%4];"
                 : "=r"(r[0]), "=r"(r[1]), "=r"(r[2]), "=r"(r[3]) : "r"(addr));
}
__device__ __forceinline__ void ldsm4t(uint32_t* r, uint32_t addr) {
    asm volatile("ldmatrix.sync.aligned.m8n8.x4.trans.shared.b16 {%0,%1,%2,%3}, [%4];"
                 : "=r"(r[0]), "=r"(r[1]), "=r"(r[2]), "=r"(r[3]) : "r"(addr));
}
__device__ __forceinline__ void mma16816(float* c, const uint32_t* a, const uint32_t* b) {
    asm volatile(
        "mma.sync.aligned.m16n8k16.row.col.f32.f16.f16.f32 "
        "{%0,%1,%2,%3}, {%4,%5,%6,%7}, {%8,%9}, {%0,%1,%2,%3};"
        : "+f"(c[0]), "+f"(c[1]), "+f"(c[2]), "+f"(c[3])
        : "r"(a[0]), "r"(a[1]), "r"(a[2]), "r"(a[3]), "r"(b[0]), "r"(b[1]));
}
__device__ __forceinline__ void cp16(uint32_t dst, const void* src) {
    asm volatile("cp.async.ca.shared.global [%0], [%1], 16;" :: "r"(dst), "l"(src));
}
__device__ __forceinline__ void cp_commit() { asm volatile("cp.async.commit_group;"); }
__device__ __forceinline__ void cp_wait0() { asm volatile("cp.async.wait_group 0;"); }

__device__ __forceinline__ void splith(float a, __half& h, __half& l) {
    h = __float2half(a);
    l = __float2half(a - __half2float(h));
}
__device__ __forceinline__ uint32_t packh(float a) {
    __half h, l;
    splith(a, h, l);
    return (uint32_t)__half_as_ushort(h) | ((uint32_t)__half_as_ushort(l) << 16);
}

// ----------------------------- weight packing --------------------------------
__global__ void pack_w_kernel(const float* __restrict__ w_reg, const float* __restrict__ w_off,
                              const float* __restrict__ b_off, const float* __restrict__ w_mod,
                              const float* __restrict__ b_mod, const float* __restrict__ w_up) {
    int i = blockIdx.x * 256 + threadIdx.x;
    if (i < 256 * K1) g_Wh[i] = __float2half(w_reg[i]);
    if (i < 32 * K1) {
        int n = i / K1;
        float v = 0.f;
        if (n < 18) v = w_off[i];
        else if (n < 27) v = w_mod[i - 18 * K1];
        g_Bomh[i] = __float2half(v);
    }
    if (i < 32) g_biasom[i] = (i < 18) ? b_off[i] : ((i < 27) ? b_mod[i - 18] : 0.f);
    if (i < 4 * 256 * K2) {
        int k = i & 1023, n = (i >> 10) & 255, p = i >> 18;
        int c = k >> 2, t = k & 3, ty = t >> 1, tx = t & 1;
        int py = p >> 1, px = p & 1;
        int kh = py ? (ty ? 2 : 0) : (ty ? 3 : 1);
        int kw = px ? (tx ? 2 : 0) : (tx ? 3 : 1);
        g_B2h[i] = __float2half(w_up[(c << 12) + (n << 4) + (kh << 2) + kw]);
    }
}

// ----------------------------- deform sampling -------------------------------
__global__ void build_v_kernel(const float* __restrict__ x) {
    int m = blockIdx.x * 256 + threadIdx.x;
    int k = blockIdx.y;
    int b = m >> 12, pix = m & 4095, h = pix >> 6, w = pix & 63;
    float oy = g_offmask[(size_t)(2 * k) * M_TOT + m];
    float ox = g_offmask[(size_t)(2 * k + 1) * M_TOT + m];
    float mr = g_offmask[(size_t)(18 + k) * M_TOT + m];
    float mask = 2.f / (1.f + expf(-mr));
    int ky = k / 3, kx = k % 3;
    float py = (float)(h - 1 + ky) + oy;
    float px = (float)(w - 1 + kx) + ox;
    float y0f = floorf(py), x0f = floorf(px);
    float wy1 = py - y0f, wx1 = px - x0f;
    float wy0 = 1.f - wy1, wx0 = 1.f - wx1;
    int y0 = (int)y0f, x0 = (int)x0f, y1 = y0 + 1, x1 = x0 + 1;
    bool vy0 = (y0 >= 0 && y0 < 64), vy1 = (y1 >= 0 && y1 < 64);
    bool vx0 = (x0 >= 0 && x0 < 64), vx1 = (x1 >= 0 && x1 < 64);
    int yc0 = min(max(y0, 0), 63), yc1 = min(max(y1, 0), 63);
    int xc0 = min(max(x0, 0), 63), xc1 = min(max(x1, 0), 63);
    int o00 = (yc0 << 6) + xc0, o01 = (yc0 << 6) + xc1;
    int o10 = (yc1 << 6) + xc0, o11 = (yc1 << 6) + xc1;
    float w00 = wy0 * wx0 * ((vy0 && vx0) ? mask : 0.f);
    float w01 = wy0 * wx1 * ((vy0 && vx1) ? mask : 0.f);
    float w10 = wy1 * wx0 * ((vy1 && vx0) ? mask : 0.f);
    float w11 = wy1 * wx1 * ((vy1 && vx1) ? mask : 0.f);
    const float* xb = x + ((size_t)b << 20);
    for (int c = 0; c < 256; c++) {
        const float* xc = xb + (c << 12);
        float v = w00 * xc[o00] + w01 * xc[o01] + w10 * xc[o10] + w11 * xc[o11];
        __half h16, l16;
        splith(v, h16, l16);
        size_t idx = (size_t)(c * 9 + k) * M_TOT + m;
        g_vh[idx] = h16;
        g_vl[idx] = l16;
    }
}

// ----------------------------- unified HMMA GEMM ------------------------------
// C(M=32768, N) = A(K,M)^T x B(N,K)^T, fp16 2-term split (ah*b + al*b), fp32 accum.
// A SMEM: K-major, 32 k-rows x 128 m-cols, 272B row stride, hi/lo planes.
// B SMEM: N-major, NTILE n-rows x 32 k-cols, 80B row stride, single plane.
// ASRC: 0 = plane arrays g_vh/g_vl (cp.async); 1 = im2col gather from x (fp32);
//       2 = tap gather from packed h1p.
// EPI:  0 = +bias -> (N,M) fp32; 1 = BN+ReLU -> packed h1p; 2 = BN+ReLU parity scatter.
template <int NTILE, int ASRC, int EPI>
__global__ __launch_bounds__(256, 2) void mma_gemm(
    const void* __restrict__ Asrc, const void* __restrict__ Asrc2,
    const __half* __restrict__ Bhg, void* __restrict__ Cout, int K,
    const float* __restrict__ p0, const float* __restrict__ p1,
    const float* __restrict__ p2, const float* __restrict__ p3) {
    constexpr int WN = (NTILE >= 128) ? 4 : 2;
    constexpr int WM = 8 / WN;
    constexpr int WARP_M = 128 / WM;
    constexpr int WARP_N = NTILE / WN;
    constexpr int MT = WARP_M / 16;
    constexpr int NTG = WARP_N / 16;
    constexpr int NT = NTG * 2;
    constexpr int A_PLANE = 32 * 272;            // 8704
    constexpr int B_PLANE = NTILE * 80;
    constexpr int B_OFF = 2 * A_PLANE;           // 17408
    constexpr int STAGE = B_OFF + B_PLANE;
    constexpr int BCH = NTILE * 4;               // cp.async 16B chunks per stage (B)
    constexpr int BJ = (BCH + 255) / 256;

    extern __shared__ char sb[];
    uint32_t sbase = smem_u32(sb);

    int t = threadIdx.x, warp = t >> 5, lane = t & 31;
    int ntile_id, par;
    if (ASRC == 2) { par = blockIdx.x >> 1; ntile_id = blockIdx.x & 1; }
    else { par = 0; ntile_id = blockIdx.x; }
    int nbase = ntile_id * NTILE;
    int m0 = blockIdx.y * 128;
    int py = par >> 1, px = par & 1;

    const __half* Bh = Bhg + ((size_t)par * 256 + nbase) * K;

    int mw = (warp / WN) * WARP_M;
    int nw = (warp % WN) * WARP_N;

    // ldmatrix lane addressing
    int g = lane >> 3;
    int a_k = (lane & 7) + ((g >> 1) << 3);
    int a_moff = (g & 1) << 3;
    uint32_t aBase = (uint32_t)(a_k * 272 + (mw + a_moff) * 2);
    int b_row = (lane & 7) | ((lane >> 4) << 3);
    int b_kh = ((lane >> 3) & 1) << 3;
    uint32_t bBase = (uint32_t)(B_OFF + (nw + b_row) * 80 + b_kh * 2);

    float acc[MT][NT][4];
#pragma unroll
    for (int i = 0; i < MT; i++)
#pragma unroll
        for (int j = 0; j < NT; j++)
#pragma unroll
            for (int e = 0; e < 4; e++) acc[i][j][e] = 0.f;

    int nch = K >> 5;

    // ---- A fill into stage s for chunk cc
    auto fillA = [&](int cc, int s) {
        int k0 = cc << 5;
        if (ASRC == 0) {
            const __half* vh = (const __half*)Asrc;
            const __half* vl = (const __half*)Asrc2;
            uint32_t base = sbase + s * STAGE;
#pragma unroll
            for (int j = 0; j < 4; j++) {
                int idx = t + j * 256;          // 1024 chunks
                int p = idx >> 9, rem = idx & 511;
                int k = rem >> 4, q = rem & 15;
                const __half* src =
                    (p ? vl : vh) + (size_t)(k0 + k) * M_TOT + m0 + q * 8;
                cp16(base + p * A_PLANE + k * 272 + q * 16, src);
            }
        } else {
            char* sA = sb + s * STAGE;
#pragma unroll
            for (int j = 0; j < 4; j++) {
                int gi = t + j * 256;           // 1024 groups of 4 m
                int k = gi >> 5, m4 = (gi & 31) << 2;
                int kk = k0 + k;
                uint32_t h01, h23, l01, l23;
                if (ASRC == 1) {
                    int c = kk / 9, tt = kk - 9 * c, ty = tt / 3, tx = tt - 3 * ty;
                    const float* xg = (const float*)Asrc;
                    uint32_t hi[4], lo[4];
#pragma unroll
                    for (int e = 0; e < 4; e++) {
                        int gm = m0 + m4 + e;
                        int b = gm >> 12, pix = gm & 4095, ii = pix >> 6, jj = pix & 63;
                        int y = ii + ty - 1, xx = jj + tx - 1;
                        bool ok = ((unsigned)y < 64u) && ((unsigned)xx < 64u);
                        float f = ok ? xg[(((size_t)(b * 256 + c)) << 12) + (y << 6) + xx] : 0.f;
                        __half h16, l16;
                        splith(f, h16, l16);
                        hi[e] = __half_as_ushort(h16);
                        lo[e] = __half_as_ushort(l16);
                    }
                    h01 = hi[0] | (hi[1] << 16); h23 = hi[2] | (hi[3] << 16);
                    l01 = lo[0] | (lo[1] << 16); l23 = lo[2] | (lo[3] << 16);
                } else {
                    int c = kk >> 2, tt = kk & 3, ty = tt >> 1, tx = tt & 1;
                    const uint32_t* hp = (const uint32_t*)Asrc;
                    uint32_t w[4];
#pragma unroll
                    for (int e = 0; e < 4; e++) {
                        int gm = m0 + m4 + e;
                        int b = gm >> 12, pix = gm & 4095, ii = pix >> 6, jj = pix & 63;
                        int r = ii + py - ty, cx = jj + px - tx;
                        bool ok = ((unsigned)r < 64u) && ((unsigned)cx < 64u);
                        w[e] = ok ? hp[(((size_t)(b * 256 + c)) << 12) + (r << 6) + cx] : 0u;
                    }
                    h01 = (w[0] & 0xFFFFu) | (w[1] << 16);
                    h23 = (w[2] & 0xFFFFu) | (w[3] << 16);
                    l01 = (w[0] >> 16) | (w[1] & 0xFFFF0000u);
                    l23 = (w[2] >> 16) | (w[3] & 0xFFFF0000u);
                }
                int off = k * 272 + m4 * 2;
                *(uint2*)(sA + off) = make_uint2(h01, h23);
                *(uint2*)(sA + A_PLANE + off) = make_uint2(l01, l23);
            }
        }
    };
    // ---- B fill via cp.async (single plane)
    auto fillB = [&](int cc, int s) {
        int k0 = cc << 5;
        uint32_t base = sbase + s * STAGE + B_OFF;
#pragma unroll
        for (int j = 0; j < BJ; j++) {
            int idx = t + j * 256;
            if (idx < BCH) {
                int r = idx >> 2, q = idx & 3;
                const __half* src = Bh + (size_t)r * K + k0 + q * 8;
                cp16(base + r * 80 + q * 16, src);
            }
        }
    };
    // ---- MMA on stage s
    auto domma = [&](int s) {
        uint32_t sA0 = sbase + s * STAGE;
#pragma unroll
        for (int ks = 0; ks < 2; ks++) {
            uint32_t aoff = sA0 + aBase + ks * 4352;
            uint32_t boff = sA0 + bBase + ks * 32;
            uint32_t ah[MT][4], bh[NTG][4];
#pragma unroll
            for (int mt = 0; mt < MT; mt++) ldsm4t(ah[mt], aoff + mt * 32);
#pragma unroll
            for (int bg = 0; bg < NTG; bg++) ldsm4(bh[bg], boff + bg * 1280);
#pragma unroll
            for (int mt = 0; mt < MT; mt++)
#pragma unroll
                for (int nt = 0; nt < NT; nt++)
                    mma16816(acc[mt][nt], ah[mt], &bh[nt >> 1][(nt & 1) * 2]);
            uint32_t al[MT][4];
#pragma unroll
            for (int mt = 0; mt < MT; mt++) ldsm4t(al[mt], aoff + A_PLANE + mt * 32);
#pragma unroll
            for (int mt = 0; mt < MT; mt++)
#pragma unroll
                for (int nt = 0; nt < NT; nt++)
                    mma16816(acc[mt][nt], al[mt], &bh[nt >> 1][(nt & 1) * 2]);
        }
    };

    // ---- prologue: fill stage 0
    fillA(0, 0);
    fillB(0, 0);
    cp_commit();
    cp_wait0();
    __syncthreads();

    for (int c = 0; c < nch; c++) {
        int s = c & 1;
        if (c + 1 < nch) {
            fillA(c + 1, s ^ 1);
            fillB(c + 1, s ^ 1);
            cp_commit();
        }
        domma(s);
        cp_wait0();
        __syncthreads();
    }

    // ---------------- epilogue ----------------
    int gi = lane >> 2, ci = (lane & 3) << 1;
#pragma unroll
    for (int mt = 0; mt < MT; mt++) {
#pragma unroll
        for (int nt = 0; nt < NT; nt++) {
            int nB = nbase + nw + nt * 8 + ci;
            int mA = m0 + mw + mt * 16 + gi;
#pragma unroll
            for (int e = 0; e < 4; e++) {
                int m = mA + ((e >> 1) << 3);
                int nn = nB + (e & 1);
                float v = acc[mt][nt][e];
                if (EPI == 0) {
                    if (nn < 27)
                        ((float*)Cout)[(size_t)nn * M_TOT + m] = v + p0[nn];
                } else {
                    float sc = p0[nn] * rsqrtf(p3[nn] + 1e-5f);
                    float r = fmaxf(v * sc + (p1[nn] - p2[nn] * sc), 0.f);
                    int b = m >> 12, pix = m & 4095;
                    if (EPI == 1) {
                        ((uint32_t*)Cout)[(((size_t)(b * 256 + nn)) << 12) + pix] =
                            packh(r);
                    } else {
                        int i2 = pix >> 6, j2 = pix & 63;
                        ((float*)Cout)[(((size_t)((b * 256 + nn) * 128 + 2 * i2 + py))
                                        << 7) + 2 * j2 + px] = r;
                    }
                }
            }
        }
    }
}

// -----------------------------------------------------------------------------
extern "C" void kernel_launch(void* const* d_in, const int* in_sizes, int n_in,
                              void* d_out, int out_size) {
    const float* x     = (const float*)d_in[0];
    const float* w_off = (const float*)d_in[1];
    const float* b_off = (const float*)d_in[2];
    const float* w_mod = (const float*)d_in[3];
    const float* b_mod = (const float*)d_in[4];
    const float* w_reg = (const float*)d_in[5];
    const float* bn1_g = (const float*)d_in[6];
    const float* bn1_b = (const float*)d_in[7];
    const float* bn1_m = (const float*)d_in[8];
    const float* bn1_v = (const float*)d_in[9];
    const float* w_up  = (const float*)d_in[10];
    const float* bn2_g = (const float*)d_in[11];
    const float* bn2_b = (const float*)d_in[12];
    const float* bn2_m = (const float*)d_in[13];
    const float* bn2_v = (const float*)d_in[14];
    float* out = (float*)d_out;

    __half *vh, *vl, *Wh, *Bomh, *B2h;
    uint32_t* h1p;
    float *om, *biasom;
    cudaGetSymbolAddress((void**)&vh,     g_vh);
    cudaGetSymbolAddress((void**)&vl,     g_vl);
    cudaGetSymbolAddress((void**)&h1p,    g_h1p);
    cudaGetSymbolAddress((void**)&om,     g_offmask);
    cudaGetSymbolAddress((void**)&biasom, g_biasom);
    cudaGetSymbolAddress((void**)&Wh,     g_Wh);
    cudaGetSymbolAddress((void**)&Bomh,   g_Bomh);
    cudaGetSymbolAddress((void**)&B2h,    g_B2h);

    const int STAGE128 = 17408 + 128 * 80;        // 27648
    const int STAGE32  = 17408 + 32 * 80;         // 19968
    const int smem128 = 2 * STAGE128;             // 55296
    const int smem32  = 2 * STAGE32;              // 39936
    cudaFuncSetAttribute(mma_gemm<32, 1, 0>,
                         cudaFuncAttributeMaxDynamicSharedMemorySize, smem32);
    cudaFuncSetAttribute(mma_gemm<128, 0, 1>,
                         cudaFuncAttributeMaxDynamicSharedMemorySize, smem128);
    cudaFuncSetAttribute(mma_gemm<128, 2, 2>,
                         cudaFuncAttributeMaxDynamicSharedMemorySize, smem128);

    // weight packing
    pack_w_kernel<<<4096, 256>>>(w_reg, w_off, b_off, w_mod, b_mod, w_up);

    // stage 0: offset/mask conv (im2col fused into GEMM A-fill)
    mma_gemm<32, 1, 0><<<dim3(1, 256), 256, smem32>>>(
        x, nullptr, Bomh, om, K1, biasom, nullptr, nullptr, nullptr);

    // stage 1: deform sampling + deform GEMM (+BN1+ReLU -> packed h1p)
    build_v_kernel<<<dim3(128, 9), 256>>>(x);
    mma_gemm<128, 0, 1><<<dim3(2, 256), 256, smem128>>>(
        vh, vl, Wh, h1p, K1, bn1_g, bn1_b, bn1_m, bn1_v);

    // stage 2: conv-transpose; A gathered from h1p per parity (+BN2+ReLU scatter)
    mma_gemm<128, 2, 2><<<dim3(8, 256), 256, smem128>>>(
        h1p, nullptr, B2h, out, K2, bn2_g, bn2_b, bn2_m, bn2_v);
}

// round 8
// speedup vs baseline: 3.6510x; 1.0114x over previous
#include <cuda_runtime.h>
#include <cuda_fp16.h>
#include <math.h>
#include <stdint.h>

#define M_TOT 32768
#define K1 2304
#define K2 1024

// ----------------------------- scratch ---------------------------------------
__device__ __half g_vh[(size_t)K1 * M_TOT];         // deform samples hi plane, (K1, M)
__device__ __half g_vl[(size_t)K1 * M_TOT];         // deform samples lo plane, (K1, M)
__device__ uint32_t g_h1p[(size_t)8 * 256 * 4096];  // stage-1 out, packed fp16 hi|lo
__device__ float    g_offmask[32u * M_TOT];         // offset/mask conv out (27 used rows)
__device__ __half g_Wh[256 * K1];                   // w_reg fp16 (N,K)
__device__ __half g_Bomh[32 * K1];                  // offset+mask weights (pad 32)
__device__ float  g_biasom[32];
__device__ __half g_B2h[4 * 256 * K2];              // convT per-parity (N,K)

// ----------------------------- helpers ---------------------------------------
__device__ __forceinline__ uint32_t smem_u32(const void* p) {
    uint32_t a;
    asm("{ .reg .u64 t; cvta.to.shared.u64 t, %1; cvt.u32.u64 %0, t; }" : "=r"(a) : "l"(p));
    return a;
}
__device__ __forceinline__ void ldsm4(uint32_t* r, uint32_t addr) {
    asm volatile("ldmatrix.sync.aligned.m8n8.x4.shared.b16 {%0,%1,%2,%3}, [%4];"
                 : "=r"(r[0]), "=r"(r[1]), "=r"(r[2]), "=r"(r[3]) : "r"(addr));
}
__device__ __forceinline__ void ldsm4t(uint32_t* r, uint32_t addr) {
    asm volatile("ldmatrix.sync.aligned.m8n8.x4.trans.shared.b16 {%0,%1,%2,%3}, [%4];"
                 : "=r"(r[0]), "=r"(r[1]), "=r"(r[2]), "=r"(r[3]) : "r"(addr));
}
__device__ __forceinline__ void mma16816(float* c, const uint32_t* a, const uint32_t* b) {
    asm volatile(
        "mma.sync.aligned.m16n8k16.row.col.f32.f16.f16.f32 "
        "{%0,%1,%2,%3}, {%4,%5,%6,%7}, {%8,%9}, {%0,%1,%2,%3};"
        : "+f"(c[0]), "+f"(c[1]), "+f"(c[2]), "+f"(c[3])
        : "r"(a[0]), "r"(a[1]), "r"(a[2]), "r"(a[3]), "r"(b[0]), "r"(b[1]));
}
__device__ __forceinline__ void cp16(uint32_t dst, const void* src) {
    asm volatile("cp.async.ca.shared.global [%0], [%1], 16;" :: "r"(dst), "l"(src));
}
__device__ __forceinline__ void cp_commit() { asm volatile("cp.async.commit_group;"); }
__device__ __forceinline__ void cp_wait0() { asm volatile("cp.async.wait_group 0;"); }
__device__ __forceinline__ void stcs(float* p, float v) {
    asm volatile("st.global.cs.f32 [%0], %1;" :: "l"(p), "f"(v));
}

__device__ __forceinline__ void splith(float a, __half& h, __half& l) {
    h = __float2half(a);
    l = __float2half(a - __half2float(h));
}
__device__ __forceinline__ uint32_t packh(float a) {
    __half h, l;
    splith(a, h, l);
    return (uint32_t)__half_as_ushort(h) | ((uint32_t)__half_as_ushort(l) << 16);
}

// ----------------------------- weight packing --------------------------------
__global__ void pack_w_kernel(const float* __restrict__ w_reg, const float* __restrict__ w_off,
                              const float* __restrict__ b_off, const float* __restrict__ w_mod,
                              const float* __restrict__ b_mod, const float* __restrict__ w_up) {
    int i = blockIdx.x * 256 + threadIdx.x;
    if (i < 256 * K1) g_Wh[i] = __float2half(w_reg[i]);
    if (i < 32 * K1) {
        int n = i / K1;
        float v = 0.f;
        if (n < 18) v = w_off[i];
        else if (n < 27) v = w_mod[i - 18 * K1];
        g_Bomh[i] = __float2half(v);
    }
    if (i < 32) g_biasom[i] = (i < 18) ? b_off[i] : ((i < 27) ? b_mod[i - 18] : 0.f);
    if (i < 4 * 256 * K2) {
        int k = i & 1023, n = (i >> 10) & 255, p = i >> 18;
        int c = k >> 2, t = k & 3, ty = t >> 1, tx = t & 1;
        int py = p >> 1, px = p & 1;
        int kh = py ? (ty ? 2 : 0) : (ty ? 3 : 1);
        int kw = px ? (tx ? 2 : 0) : (tx ? 3 : 1);
        g_B2h[i] = __float2half(w_up[(c << 12) + (n << 4) + (kh << 2) + kw]);
    }
}

// ----------------------------- deform sampling -------------------------------
__global__ void build_v_kernel(const float* __restrict__ x) {
    int m = blockIdx.x * 256 + threadIdx.x;
    int k = blockIdx.y;
    int b = m >> 12, pix = m & 4095, h = pix >> 6, w = pix & 63;
    float oy = g_offmask[(size_t)(2 * k) * M_TOT + m];
    float ox = g_offmask[(size_t)(2 * k + 1) * M_TOT + m];
    float mr = g_offmask[(size_t)(18 + k) * M_TOT + m];
    float mask = 2.f / (1.f + expf(-mr));
    int ky = k / 3, kx = k % 3;
    float py = (float)(h - 1 + ky) + oy;
    float px = (float)(w - 1 + kx) + ox;
    float y0f = floorf(py), x0f = floorf(px);
    float wy1 = py - y0f, wx1 = px - x0f;
    float wy0 = 1.f - wy1, wx0 = 1.f - wx1;
    int y0 = (int)y0f, x0 = (int)x0f, y1 = y0 + 1, x1 = x0 + 1;
    bool vy0 = (y0 >= 0 && y0 < 64), vy1 = (y1 >= 0 && y1 < 64);
    bool vx0 = (x0 >= 0 && x0 < 64), vx1 = (x1 >= 0 && x1 < 64);
    int yc0 = min(max(y0, 0), 63), yc1 = min(max(y1, 0), 63);
    int xc0 = min(max(x0, 0), 63), xc1 = min(max(x1, 0), 63);
    int o00 = (yc0 << 6) + xc0, o01 = (yc0 << 6) + xc1;
    int o10 = (yc1 << 6) + xc0, o11 = (yc1 << 6) + xc1;
    float w00 = wy0 * wx0 * ((vy0 && vx0) ? mask : 0.f);
    float w01 = wy0 * wx1 * ((vy0 && vx1) ? mask : 0.f);
    float w10 = wy1 * wx0 * ((vy1 && vx0) ? mask : 0.f);
    float w11 = wy1 * wx1 * ((vy1 && vx1) ? mask : 0.f);
    const float* xb = x + ((size_t)b << 20);
    for (int c = 0; c < 256; c++) {
        const float* xc = xb + (c << 12);
        float v = w00 * xc[o00] + w01 * xc[o01] + w10 * xc[o10] + w11 * xc[o11];
        __half h16, l16;
        splith(v, h16, l16);
        size_t idx = (size_t)(c * 9 + k) * M_TOT + m;
        g_vh[idx] = h16;
        g_vl[idx] = l16;
    }
}

// ----------------------------- unified HMMA GEMM ------------------------------
// C(M=32768, N) = A(K,M)^T x B(N,K)^T, fp16 2-term split (ah*b + al*b), fp32 accum.
// A SMEM: K-major, 32 k-rows x 128 m-cols, 272B row stride, hi/lo planes.
// B SMEM: N-major, NTILE n-rows x 32 k-cols, 80B row stride, single plane.
// ASRC: 0 = plane arrays g_vh/g_vl (cp.async); 1 = im2col gather from x (fp32);
//       2 = tap gather from packed h1p.
// EPI:  0 = +bias -> (N,M) fp32; 1 = BN+ReLU -> packed h1p; 2 = BN+ReLU parity scatter.
template <int NTILE, int ASRC, int EPI>
__global__ __launch_bounds__(256, 2) void mma_gemm(
    const void* __restrict__ Asrc, const void* __restrict__ Asrc2,
    const __half* __restrict__ Bhg, void* __restrict__ Cout, int K,
    const float* __restrict__ p0, const float* __restrict__ p1,
    const float* __restrict__ p2, const float* __restrict__ p3) {
    constexpr int WN = (NTILE >= 128) ? 4 : 2;
    constexpr int WM = 8 / WN;
    constexpr int WARP_M = 128 / WM;
    constexpr int WARP_N = NTILE / WN;
    constexpr int MT = WARP_M / 16;
    constexpr int NTG = WARP_N / 16;
    constexpr int NT = NTG * 2;
    constexpr int A_PLANE = 32 * 272;            // 8704
    constexpr int B_PLANE = NTILE * 80;
    constexpr int B_OFF = 2 * A_PLANE;           // 17408
    constexpr int STAGE = B_OFF + B_PLANE;
    constexpr int BCH = NTILE * 4;               // cp.async 16B chunks per stage (B)
    constexpr int BJ = (BCH + 255) / 256;

    extern __shared__ char sb[];
    uint32_t sbase = smem_u32(sb);

    int t = threadIdx.x, warp = t >> 5, lane = t & 31;
    int ntile_id, par;
    if (ASRC == 2) { par = blockIdx.x >> 1; ntile_id = blockIdx.x & 1; }
    else { par = 0; ntile_id = blockIdx.x; }
    int nbase = ntile_id * NTILE;
    int m0 = blockIdx.y * 128;
    int py = par >> 1, px = par & 1;

    const __half* Bh = Bhg + ((size_t)par * 256 + nbase) * K;

    int mw = (warp / WN) * WARP_M;
    int nw = (warp % WN) * WARP_N;

    // ldmatrix lane addressing
    int g = lane >> 3;
    int a_k = (lane & 7) + ((g >> 1) << 3);
    int a_moff = (g & 1) << 3;
    uint32_t aBase = (uint32_t)(a_k * 272 + (mw + a_moff) * 2);
    int b_row = (lane & 7) | ((lane >> 4) << 3);
    int b_kh = ((lane >> 3) & 1) << 3;
    uint32_t bBase = (uint32_t)(B_OFF + (nw + b_row) * 80 + b_kh * 2);

    float acc[MT][NT][4];
#pragma unroll
    for (int i = 0; i < MT; i++)
#pragma unroll
        for (int j = 0; j < NT; j++)
#pragma unroll
            for (int e = 0; e < 4; e++) acc[i][j][e] = 0.f;

    int nch = K >> 5;

    // ---- gather-path A staging registers (held across domma)
    uint32_t wreg[16];   // ASRC 2: 16 packed words; ASRC 1: 8 hi + 8 lo pairs

    // ---- A gather: global -> regs for chunk cc (ASRC 1/2 only)
    auto loadA = [&](int cc) {
        int k0 = cc << 5;
#pragma unroll
        for (int j = 0; j < 4; j++) {
            int gi = t + j * 256;           // 1024 groups of 4 m
            int k = gi >> 5, m4 = (gi & 31) << 2;
            int kk = k0 + k;
            if (ASRC == 1) {
                int c = kk / 9, tt = kk - 9 * c, ty = tt / 3, tx = tt - 3 * ty;
                const float* xg = (const float*)Asrc;
#pragma unroll
                for (int e = 0; e < 4; e++) {
                    int gm = m0 + m4 + e;
                    int b = gm >> 12, pix = gm & 4095, ii = pix >> 6, jj = pix & 63;
                    int y = ii + ty - 1, xx = jj + tx - 1;
                    bool ok = ((unsigned)y < 64u) && ((unsigned)xx < 64u);
                    float f = ok ? xg[(((size_t)(b * 256 + c)) << 12) + (y << 6) + xx] : 0.f;
                    wreg[j * 4 + e] = __float_as_uint(f);
                }
            } else if (ASRC == 2) {
                int c = kk >> 2, tt = kk & 3, ty = tt >> 1, tx = tt & 1;
                const uint32_t* hp = (const uint32_t*)Asrc;
#pragma unroll
                for (int e = 0; e < 4; e++) {
                    int gm = m0 + m4 + e;
                    int b = gm >> 12, pix = gm & 4095, ii = pix >> 6, jj = pix & 63;
                    int r = ii + py - ty, cx = jj + px - tx;
                    bool ok = ((unsigned)r < 64u) && ((unsigned)cx < 64u);
                    wreg[j * 4 + e] =
                        ok ? hp[(((size_t)(b * 256 + c)) << 12) + (r << 6) + cx] : 0u;
                }
            }
        }
    };
    // ---- A store: regs -> SMEM stage s (ASRC 1/2 only)
    auto storeA = [&](int s) {
        char* sA = sb + s * STAGE;
#pragma unroll
        for (int j = 0; j < 4; j++) {
            int gi = t + j * 256;
            int k = gi >> 5, m4 = (gi & 31) << 2;
            uint32_t h01, h23, l01, l23;
            if (ASRC == 1) {
                uint32_t hi[4], lo[4];
#pragma unroll
                for (int e = 0; e < 4; e++) {
                    float f = __uint_as_float(wreg[j * 4 + e]);
                    __half h16, l16;
                    splith(f, h16, l16);
                    hi[e] = __half_as_ushort(h16);
                    lo[e] = __half_as_ushort(l16);
                }
                h01 = hi[0] | (hi[1] << 16); h23 = hi[2] | (hi[3] << 16);
                l01 = lo[0] | (lo[1] << 16); l23 = lo[2] | (lo[3] << 16);
            } else {
                uint32_t* w = &wreg[j * 4];
                h01 = (w[0] & 0xFFFFu) | (w[1] << 16);
                h23 = (w[2] & 0xFFFFu) | (w[3] << 16);
                l01 = (w[0] >> 16) | (w[1] & 0xFFFF0000u);
                l23 = (w[2] >> 16) | (w[3] & 0xFFFF0000u);
            }
            int off = k * 272 + m4 * 2;
            *(uint2*)(sA + off) = make_uint2(h01, h23);
            *(uint2*)(sA + A_PLANE + off) = make_uint2(l01, l23);
        }
    };
    // ---- A fill via cp.async (ASRC 0 only)
    auto fillA_async = [&](int cc, int s) {
        int k0 = cc << 5;
        const __half* vh = (const __half*)Asrc;
        const __half* vl = (const __half*)Asrc2;
        uint32_t base = sbase + s * STAGE;
#pragma unroll
        for (int j = 0; j < 4; j++) {
            int idx = t + j * 256;          // 1024 chunks
            int p = idx >> 9, rem = idx & 511;
            int k = rem >> 4, q = rem & 15;
            const __half* src = (p ? vl : vh) + (size_t)(k0 + k) * M_TOT + m0 + q * 8;
            cp16(base + p * A_PLANE + k * 272 + q * 16, src);
        }
    };
    // ---- B fill via cp.async (single plane)
    auto fillB = [&](int cc, int s) {
        int k0 = cc << 5;
        uint32_t base = sbase + s * STAGE + B_OFF;
#pragma unroll
        for (int j = 0; j < BJ; j++) {
            int idx = t + j * 256;
            if (idx < BCH) {
                int r = idx >> 2, q = idx & 3;
                const __half* src = Bh + (size_t)r * K + k0 + q * 8;
                cp16(base + r * 80 + q * 16, src);
            }
        }
    };
    // ---- MMA on stage s
    auto domma = [&](int s) {
        uint32_t sA0 = sbase + s * STAGE;
#pragma unroll
        for (int ks = 0; ks < 2; ks++) {
            uint32_t aoff = sA0 + aBase + ks * 4352;
            uint32_t boff = sA0 + bBase + ks * 32;
            uint32_t ah[MT][4], bh[NTG][4];
#pragma unroll
            for (int mt = 0; mt < MT; mt++) ldsm4t(ah[mt], aoff + mt * 32);
#pragma unroll
            for (int bg = 0; bg < NTG; bg++) ldsm4(bh[bg], boff + bg * 1280);
#pragma unroll
            for (int mt = 0; mt < MT; mt++)
#pragma unroll
                for (int nt = 0; nt < NT; nt++)
                    mma16816(acc[mt][nt], ah[mt], &bh[nt >> 1][(nt & 1) * 2]);
            uint32_t al[MT][4];
#pragma unroll
            for (int mt = 0; mt < MT; mt++) ldsm4t(al[mt], aoff + A_PLANE + mt * 32);
#pragma unroll
            for (int mt = 0; mt < MT; mt++)
#pragma unroll
                for (int nt = 0; nt < NT; nt++)
                    mma16816(acc[mt][nt], al[mt], &bh[nt >> 1][(nt & 1) * 2]);
        }
    };

    // ---- prologue: fill stage 0
    if (ASRC == 0) fillA_async(0, 0);
    else { loadA(0); storeA(0); }
    fillB(0, 0);
    cp_commit();
    cp_wait0();
    __syncthreads();

    for (int c = 0; c < nch; c++) {
        int s = c & 1;
        if (c + 1 < nch) {
            if (ASRC == 0) fillA_async(c + 1, s ^ 1);
            else loadA(c + 1);               // LDGs in flight across domma
            fillB(c + 1, s ^ 1);
            cp_commit();
        }
        domma(s);
        if (ASRC != 0 && c + 1 < nch) storeA(s ^ 1);
        cp_wait0();
        __syncthreads();
    }

    // ---------------- epilogue ----------------
    int gi = lane >> 2, ci = (lane & 3) << 1;
#pragma unroll
    for (int mt = 0; mt < MT; mt++) {
#pragma unroll
        for (int nt = 0; nt < NT; nt++) {
            int nB = nbase + nw + nt * 8 + ci;
            int mA = m0 + mw + mt * 16 + gi;
#pragma unroll
            for (int e = 0; e < 4; e++) {
                int m = mA + ((e >> 1) << 3);
                int nn = nB + (e & 1);
                float v = acc[mt][nt][e];
                if (EPI == 0) {
                    if (nn < 27)
                        ((float*)Cout)[(size_t)nn * M_TOT + m] = v + p0[nn];
                } else {
                    float sc = p0[nn] * rsqrtf(p3[nn] + 1e-5f);
                    float r = fmaxf(v * sc + (p1[nn] - p2[nn] * sc), 0.f);
                    int b = m >> 12, pix = m & 4095;
                    if (EPI == 1) {
                        ((uint32_t*)Cout)[(((size_t)(b * 256 + nn)) << 12) + pix] =
                            packh(r);
                    } else {
                        int i2 = pix >> 6, j2 = pix & 63;
                        stcs(&((float*)Cout)[(((size_t)((b * 256 + nn) * 128 +
                              2 * i2 + py)) << 7) + 2 * j2 + px], r);
                    }
                }
            }
        }
    }
}

// -----------------------------------------------------------------------------
extern "C" void kernel_launch(void* const* d_in, const int* in_sizes, int n_in,
                              void* d_out, int out_size) {
    const float* x     = (const float*)d_in[0];
    const float* w_off = (const float*)d_in[1];
    const float* b_off = (const float*)d_in[2];
    const float* w_mod = (const float*)d_in[3];
    const float* b_mod = (const float*)d_in[4];
    const float* w_reg = (const float*)d_in[5];
    const float* bn1_g = (const float*)d_in[6];
    const float* bn1_b = (const float*)d_in[7];
    const float* bn1_m = (const float*)d_in[8];
    const float* bn1_v = (const float*)d_in[9];
    const float* w_up  = (const float*)d_in[10];
    const float* bn2_g = (const float*)d_in[11];
    const float* bn2_b = (const float*)d_in[12];
    const float* bn2_m = (const float*)d_in[13];
    const float* bn2_v = (const float*)d_in[14];
    float* out = (float*)d_out;

    __half *vh, *vl, *Wh, *Bomh, *B2h;
    uint32_t* h1p;
    float *om, *biasom;
    cudaGetSymbolAddress((void**)&vh,     g_vh);
    cudaGetSymbolAddress((void**)&vl,     g_vl);
    cudaGetSymbolAddress((void**)&h1p,    g_h1p);
    cudaGetSymbolAddress((void**)&om,     g_offmask);
    cudaGetSymbolAddress((void**)&biasom, g_biasom);
    cudaGetSymbolAddress((void**)&Wh,     g_Wh);
    cudaGetSymbolAddress((void**)&Bomh,   g_Bomh);
    cudaGetSymbolAddress((void**)&B2h,    g_B2h);

    const int STAGE128 = 17408 + 128 * 80;        // 27648
    const int STAGE32  = 17408 + 32 * 80;         // 19968
    const int smem128 = 2 * STAGE128;             // 55296
    const int smem32  = 2 * STAGE32;              // 39936
    cudaFuncSetAttribute(mma_gemm<32, 1, 0>,
                         cudaFuncAttributeMaxDynamicSharedMemorySize, smem32);
    cudaFuncSetAttribute(mma_gemm<128, 0, 1>,
                         cudaFuncAttributeMaxDynamicSharedMemorySize, smem128);
    cudaFuncSetAttribute(mma_gemm<128, 2, 2>,
                         cudaFuncAttributeMaxDynamicSharedMemorySize, smem128);

    // weight packing
    pack_w_kernel<<<4096, 256>>>(w_reg, w_off, b_off, w_mod, b_mod, w_up);

    // stage 0: offset/mask conv (im2col fused into GEMM A-fill)
    mma_gemm<32, 1, 0><<<dim3(1, 256), 256, smem32>>>(
        x, nullptr, Bomh, om, K1, biasom, nullptr, nullptr, nullptr);

    // stage 1: deform sampling + deform GEMM (+BN1+ReLU -> packed h1p)
    build_v_kernel<<<dim3(128, 9), 256>>>(x);
    mma_gemm<128, 0, 1><<<dim3(2, 256), 256, smem128>>>(
        vh, vl, Wh, h1p, K1, bn1_g, bn1_b, bn1_m, bn1_v);

    // stage 2: conv-transpose; A gathered from h1p per parity (+BN2+ReLU scatter)
    mma_gemm<128, 2, 2><<<dim3(8, 256), 256, smem128>>>(
        h1p, nullptr, B2h, out, K2, bn2_g, bn2_b, bn2_m, bn2_v);
}

// round 9
// speedup vs baseline: 4.3450x; 1.1901x over previous
#include <cuda_runtime.h>
#include <cuda_fp16.h>
#include <math.h>
#include <stdint.h>

#define M_TOT 32768
#define K1 2304
#define K2 1024

// ----------------------------- scratch ---------------------------------------
__device__ __half g_vh[(size_t)K1 * M_TOT];         // deform samples hi plane, (K1, M)
__device__ __half g_vl[(size_t)K1 * M_TOT];         // deform samples lo plane, (K1, M)
__device__ __half g_h1h[(size_t)8 * 256 * 4096];    // stage-1 out, fp16 (b,c,pix)
__device__ float  g_offmask[32u * M_TOT];           // offset/mask conv out (27 used rows)
__device__ __half g_Wh[256 * K1];                   // w_reg fp16 (N,K)
__device__ __half g_Bomh[32 * K1];                  // offset+mask weights (pad 32)
__device__ float  g_biasom[32];
__device__ __half g_B2h[4 * 256 * K2];              // convT per-parity (N,K)

// ----------------------------- helpers ---------------------------------------
__device__ __forceinline__ uint32_t smem_u32(const void* p) {
    uint32_t a;
    asm("{ .reg .u64 t; cvta.to.shared.u64 t, %1; cvt.u32.u64 %0, t; }" : "=r"(a) : "l"(p));
    return a;
}
__device__ __forceinline__ void ldsm4(uint32_t* r, uint32_t addr) {
    asm volatile("ldmatrix.sync.aligned.m8n8.x4.shared.b16 {%0,%1,%2,%3}, [%4];"
                 : "=r"(r[0]), "=r"(r[1]), "=r"(r[2]), "=r"(r[3]) : "r"(addr));
}
__device__ __forceinline__ void ldsm4t(uint32_t* r, uint32_t addr) {
    asm volatile("ldmatrix.sync.aligned.m8n8.x4.trans.shared.b16 {%0,%1,%2,%3}, [%4];"
                 : "=r"(r[0]), "=r"(r[1]), "=r"(r[2]), "=r"(r[3]) : "r"(addr));
}
__device__ __forceinline__ void mma16816(float* c, const uint32_t* a, const uint32_t* b) {
    asm volatile(
        "mma.sync.aligned.m16n8k16.row.col.f32.f16.f16.f32 "
        "{%0,%1,%2,%3}, {%4,%5,%6,%7}, {%8,%9}, {%0,%1,%2,%3};"
        : "+f"(c[0]), "+f"(c[1]), "+f"(c[2]), "+f"(c[3])
        : "r"(a[0]), "r"(a[1]), "r"(a[2]), "r"(a[3]), "r"(b[0]), "r"(b[1]));
}
__device__ __forceinline__ void cp16(uint32_t dst, const void* src) {
    asm volatile("cp.async.ca.shared.global [%0], [%1], 16;" :: "r"(dst), "l"(src));
}
__device__ __forceinline__ void cp_commit() { asm volatile("cp.async.commit_group;"); }
__device__ __forceinline__ void cp_wait0() { asm volatile("cp.async.wait_group 0;"); }
__device__ __forceinline__ void stcs(float* p, float v) {
    asm volatile("st.global.cs.f32 [%0], %1;" :: "l"(p), "f"(v));
}

__device__ __forceinline__ void splith(float a, __half& h, __half& l) {
    h = __float2half(a);
    l = __float2half(a - __half2float(h));
}

// ----------------------------- weight packing --------------------------------
__global__ void pack_w_kernel(const float* __restrict__ w_reg, const float* __restrict__ w_off,
                              const float* __restrict__ b_off, const float* __restrict__ w_mod,
                              const float* __restrict__ b_mod, const float* __restrict__ w_up) {
    int i = blockIdx.x * 256 + threadIdx.x;
    if (i < 256 * K1) g_Wh[i] = __float2half(w_reg[i]);
    if (i < 32 * K1) {
        int n = i / K1;
        float v = 0.f;
        if (n < 18) v = w_off[i];
        else if (n < 27) v = w_mod[i - 18 * K1];
        g_Bomh[i] = __float2half(v);
    }
    if (i < 32) g_biasom[i] = (i < 18) ? b_off[i] : ((i < 27) ? b_mod[i - 18] : 0.f);
    if (i < 4 * 256 * K2) {
        int k = i & 1023, n = (i >> 10) & 255, p = i >> 18;
        int c = k >> 2, t = k & 3, ty = t >> 1, tx = t & 1;
        int py = p >> 1, px = p & 1;
        int kh = py ? (ty ? 2 : 0) : (ty ? 3 : 1);
        int kw = px ? (tx ? 2 : 0) : (tx ? 3 : 1);
        g_B2h[i] = __float2half(w_up[(c << 12) + (n << 4) + (kh << 2) + kw]);
    }
}

// ----------------------------- deform sampling -------------------------------
__global__ void build_v_kernel(const float* __restrict__ x) {
    int m = blockIdx.x * 256 + threadIdx.x;
    int k = blockIdx.y;
    int b = m >> 12, pix = m & 4095, h = pix >> 6, w = pix & 63;
    float oy = g_offmask[(size_t)(2 * k) * M_TOT + m];
    float ox = g_offmask[(size_t)(2 * k + 1) * M_TOT + m];
    float mr = g_offmask[(size_t)(18 + k) * M_TOT + m];
    float mask = 2.f / (1.f + expf(-mr));
    int ky = k / 3, kx = k % 3;
    float py = (float)(h - 1 + ky) + oy;
    float px = (float)(w - 1 + kx) + ox;
    float y0f = floorf(py), x0f = floorf(px);
    float wy1 = py - y0f, wx1 = px - x0f;
    float wy0 = 1.f - wy1, wx0 = 1.f - wx1;
    int y0 = (int)y0f, x0 = (int)x0f, y1 = y0 + 1, x1 = x0 + 1;
    bool vy0 = (y0 >= 0 && y0 < 64), vy1 = (y1 >= 0 && y1 < 64);
    bool vx0 = (x0 >= 0 && x0 < 64), vx1 = (x1 >= 0 && x1 < 64);
    int yc0 = min(max(y0, 0), 63), yc1 = min(max(y1, 0), 63);
    int xc0 = min(max(x0, 0), 63), xc1 = min(max(x1, 0), 63);
    int o00 = (yc0 << 6) + xc0, o01 = (yc0 << 6) + xc1;
    int o10 = (yc1 << 6) + xc0, o11 = (yc1 << 6) + xc1;
    float w00 = wy0 * wx0 * ((vy0 && vx0) ? mask : 0.f);
    float w01 = wy0 * wx1 * ((vy0 && vx1) ? mask : 0.f);
    float w10 = wy1 * wx0 * ((vy1 && vx0) ? mask : 0.f);
    float w11 = wy1 * wx1 * ((vy1 && vx1) ? mask : 0.f);
    const float* xb = x + ((size_t)b << 20);
    for (int c = 0; c < 256; c++) {
        const float* xc = xb + (c << 12);
        float v = w00 * xc[o00] + w01 * xc[o01] + w10 * xc[o10] + w11 * xc[o11];
        __half h16, l16;
        splith(v, h16, l16);
        size_t idx = (size_t)(c * 9 + k) * M_TOT + m;
        g_vh[idx] = h16;
        g_vl[idx] = l16;
    }
}

// ----------------------------- unified HMMA GEMM ------------------------------
// C(M=32768, N) = A(K,M)^T x B(N,K)^T, fp16, fp32 accum.
// SPLIT = A planes: 2 = compensated (ah*b + al*b); 1 = plain fp16.
// A SMEM: K-major, 32 k-rows x 128 m-cols, 272B row stride, SPLIT planes.
// B SMEM: N-major, NTILE n-rows x 32 k-cols, 80B row stride, single plane.
// ASRC: 0 = plane arrays g_vh/g_vl (cp.async); 1 = im2col gather from x (fp32);
//       2 = tap gather from fp16 h1.
// EPI:  0 = +bias -> (N,M) fp32; 1 = BN+ReLU -> fp16 h1; 2 = BN+ReLU parity scatter.
template <int NTILE, int ASRC, int EPI, int SPLIT>
__global__ __launch_bounds__(256, 2) void mma_gemm(
    const void* __restrict__ Asrc, const void* __restrict__ Asrc2,
    const __half* __restrict__ Bhg, void* __restrict__ Cout, int K,
    const float* __restrict__ p0, const float* __restrict__ p1,
    const float* __restrict__ p2, const float* __restrict__ p3) {
    constexpr int WN = (NTILE >= 128) ? 4 : 2;
    constexpr int WM = 8 / WN;
    constexpr int WARP_M = 128 / WM;
    constexpr int WARP_N = NTILE / WN;
    constexpr int MT = WARP_M / 16;
    constexpr int NTG = WARP_N / 16;
    constexpr int NT = NTG * 2;
    constexpr int A_PLANE = 32 * 272;            // 8704
    constexpr int B_PLANE = NTILE * 80;
    constexpr int B_OFF = SPLIT * A_PLANE;
    constexpr int STAGE = B_OFF + B_PLANE;
    constexpr int BCH = NTILE * 4;               // cp.async 16B chunks per stage (B)
    constexpr int BJ = (BCH + 255) / 256;

    extern __shared__ char sb[];
    uint32_t sbase = smem_u32(sb);

    int t = threadIdx.x, warp = t >> 5, lane = t & 31;
    int ntile_id, par;
    if (ASRC == 2) { par = blockIdx.x >> 1; ntile_id = blockIdx.x & 1; }
    else { par = 0; ntile_id = blockIdx.x; }
    int nbase = ntile_id * NTILE;
    int m0 = blockIdx.y * 128;
    int py = par >> 1, px = par & 1;

    const __half* Bh = Bhg + ((size_t)par * 256 + nbase) * K;

    int mw = (warp / WN) * WARP_M;
    int nw = (warp % WN) * WARP_N;

    // ldmatrix lane addressing
    int g = lane >> 3;
    int a_k = (lane & 7) + ((g >> 1) << 3);
    int a_moff = (g & 1) << 3;
    uint32_t aBase = (uint32_t)(a_k * 272 + (mw + a_moff) * 2);
    int b_row = (lane & 7) | ((lane >> 4) << 3);
    int b_kh = ((lane >> 3) & 1) << 3;
    uint32_t bBase = (uint32_t)(B_OFF + (nw + b_row) * 80 + b_kh * 2);

    float acc[MT][NT][4];
#pragma unroll
    for (int i = 0; i < MT; i++)
#pragma unroll
        for (int j = 0; j < NT; j++)
#pragma unroll
            for (int e = 0; e < 4; e++) acc[i][j][e] = 0.f;

    int nch = K >> 5;

    // ---- gather-path A staging registers (held across domma)
    uint32_t wreg[16];

    // ---- A gather: global -> regs for chunk cc (ASRC 1/2 only)
    auto loadA = [&](int cc) {
        int k0 = cc << 5;
#pragma unroll
        for (int j = 0; j < 4; j++) {
            int gi = t + j * 256;           // 1024 groups of 4 m
            int k = gi >> 5, m4 = (gi & 31) << 2;
            int kk = k0 + k;
            if (ASRC == 1) {
                int c = kk / 9, tt = kk - 9 * c, ty = tt / 3, tx = tt - 3 * ty;
                const float* xg = (const float*)Asrc;
#pragma unroll
                for (int e = 0; e < 4; e++) {
                    int gm = m0 + m4 + e;
                    int b = gm >> 12, pix = gm & 4095, ii = pix >> 6, jj = pix & 63;
                    int y = ii + ty - 1, xx = jj + tx - 1;
                    bool ok = ((unsigned)y < 64u) && ((unsigned)xx < 64u);
                    float f = ok ? xg[(((size_t)(b * 256 + c)) << 12) + (y << 6) + xx] : 0.f;
                    wreg[j * 4 + e] = __float_as_uint(f);
                }
            } else if (ASRC == 2) {
                int c = kk >> 2, tt = kk & 3, ty = tt >> 1, tx = tt & 1;
                const __half* hp = (const __half*)Asrc;
#pragma unroll
                for (int e = 0; e < 4; e++) {
                    int gm = m0 + m4 + e;
                    int b = gm >> 12, pix = gm & 4095, ii = pix >> 6, jj = pix & 63;
                    int r = ii + py - ty, cx = jj + px - tx;
                    bool ok = ((unsigned)r < 64u) && ((unsigned)cx < 64u);
                    wreg[j * 4 + e] = ok
                        ? (uint32_t)__half_as_ushort(
                              hp[(((size_t)(b * 256 + c)) << 12) + (r << 6) + cx])
                        : 0u;
                }
            }
        }
    };
    // ---- A store: regs -> SMEM stage s (ASRC 1/2 only)
    auto storeA = [&](int s) {
        char* sA = sb + s * STAGE;
#pragma unroll
        for (int j = 0; j < 4; j++) {
            int gi = t + j * 256;
            int k = gi >> 5, m4 = (gi & 31) << 2;
            int off = k * 272 + m4 * 2;
            if (ASRC == 1) {
                uint32_t hi[4], lo[4];
#pragma unroll
                for (int e = 0; e < 4; e++) {
                    float f = __uint_as_float(wreg[j * 4 + e]);
                    __half h16, l16;
                    splith(f, h16, l16);
                    hi[e] = __half_as_ushort(h16);
                    lo[e] = __half_as_ushort(l16);
                }
                *(uint2*)(sA + off) =
                    make_uint2(hi[0] | (hi[1] << 16), hi[2] | (hi[3] << 16));
                if (SPLIT == 2)
                    *(uint2*)(sA + A_PLANE + off) =
                        make_uint2(lo[0] | (lo[1] << 16), lo[2] | (lo[3] << 16));
            } else {
                uint32_t* w = &wreg[j * 4];
                *(uint2*)(sA + off) =
                    make_uint2(w[0] | (w[1] << 16), w[2] | (w[3] << 16));
            }
        }
    };
    // ---- A fill via cp.async (ASRC 0 only, SPLIT==2)
    auto fillA_async = [&](int cc, int s) {
        int k0 = cc << 5;
        const __half* vh = (const __half*)Asrc;
        const __half* vl = (const __half*)Asrc2;
        uint32_t base = sbase + s * STAGE;
#pragma unroll
        for (int j = 0; j < 4; j++) {
            int idx = t + j * 256;          // 1024 chunks
            int p = idx >> 9, rem = idx & 511;
            int k = rem >> 4, q = rem & 15;
            const __half* src = (p ? vl : vh) + (size_t)(k0 + k) * M_TOT + m0 + q * 8;
            cp16(base + p * A_PLANE + k * 272 + q * 16, src);
        }
    };
    // ---- B fill via cp.async (single plane)
    auto fillB = [&](int cc, int s) {
        int k0 = cc << 5;
        uint32_t base = sbase + s * STAGE + B_OFF;
#pragma unroll
        for (int j = 0; j < BJ; j++) {
            int idx = t + j * 256;
            if (idx < BCH) {
                int r = idx >> 2, q = idx & 3;
                const __half* src = Bh + (size_t)r * K + k0 + q * 8;
                cp16(base + r * 80 + q * 16, src);
            }
        }
    };
    // ---- MMA on stage s
    auto domma = [&](int s) {
        uint32_t sA0 = sbase + s * STAGE;
#pragma unroll
        for (int ks = 0; ks < 2; ks++) {
            uint32_t aoff = sA0 + aBase + ks * 4352;
            uint32_t boff = sA0 + bBase + ks * 32;
            uint32_t ah[MT][4], bh[NTG][4];
#pragma unroll
            for (int mt = 0; mt < MT; mt++) ldsm4t(ah[mt], aoff + mt * 32);
#pragma unroll
            for (int bg = 0; bg < NTG; bg++) ldsm4(bh[bg], boff + bg * 1280);
#pragma unroll
            for (int mt = 0; mt < MT; mt++)
#pragma unroll
                for (int nt = 0; nt < NT; nt++)
                    mma16816(acc[mt][nt], ah[mt], &bh[nt >> 1][(nt & 1) * 2]);
            if (SPLIT == 2) {
                uint32_t al[MT][4];
#pragma unroll
                for (int mt = 0; mt < MT; mt++) ldsm4t(al[mt], aoff + A_PLANE + mt * 32);
#pragma unroll
                for (int mt = 0; mt < MT; mt++)
#pragma unroll
                    for (int nt = 0; nt < NT; nt++)
                        mma16816(acc[mt][nt], al[mt], &bh[nt >> 1][(nt & 1) * 2]);
            }
        }
    };

    // ---- prologue: fill stage 0
    if (ASRC == 0) fillA_async(0, 0);
    else { loadA(0); storeA(0); }
    fillB(0, 0);
    cp_commit();
    cp_wait0();
    __syncthreads();

    for (int c = 0; c < nch; c++) {
        int s = c & 1;
        if (c + 1 < nch) {
            if (ASRC == 0) fillA_async(c + 1, s ^ 1);
            else loadA(c + 1);               // LDGs in flight across domma
            fillB(c + 1, s ^ 1);
            cp_commit();
        }
        domma(s);
        if (ASRC != 0 && c + 1 < nch) storeA(s ^ 1);
        cp_wait0();
        __syncthreads();
    }

    // ---------------- epilogue ----------------
    int gi = lane >> 2, ci = (lane & 3) << 1;
#pragma unroll
    for (int mt = 0; mt < MT; mt++) {
#pragma unroll
        for (int nt = 0; nt < NT; nt++) {
            int nB = nbase + nw + nt * 8 + ci;
            int mA = m0 + mw + mt * 16 + gi;
#pragma unroll
            for (int e = 0; e < 4; e++) {
                int m = mA + ((e >> 1) << 3);
                int nn = nB + (e & 1);
                float v = acc[mt][nt][e];
                if (EPI == 0) {
                    if (nn < 27)
                        ((float*)Cout)[(size_t)nn * M_TOT + m] = v + p0[nn];
                } else {
                    float sc = p0[nn] * rsqrtf(p3[nn] + 1e-5f);
                    float r = fmaxf(v * sc + (p1[nn] - p2[nn] * sc), 0.f);
                    int b = m >> 12, pix = m & 4095;
                    if (EPI == 1) {
                        ((__half*)Cout)[(((size_t)(b * 256 + nn)) << 12) + pix] =
                            __float2half(r);
                    } else {
                        int i2 = pix >> 6, j2 = pix & 63;
                        stcs(&((float*)Cout)[(((size_t)((b * 256 + nn) * 128 +
                              2 * i2 + py)) << 7) + 2 * j2 + px], r);
                    }
                }
            }
        }
    }
}

// -----------------------------------------------------------------------------
extern "C" void kernel_launch(void* const* d_in, const int* in_sizes, int n_in,
                              void* d_out, int out_size) {
    const float* x     = (const float*)d_in[0];
    const float* w_off = (const float*)d_in[1];
    const float* b_off = (const float*)d_in[2];
    const float* w_mod = (const float*)d_in[3];
    const float* b_mod = (const float*)d_in[4];
    const float* w_reg = (const float*)d_in[5];
    const float* bn1_g = (const float*)d_in[6];
    const float* bn1_b = (const float*)d_in[7];
    const float* bn1_m = (const float*)d_in[8];
    const float* bn1_v = (const float*)d_in[9];
    const float* w_up  = (const float*)d_in[10];
    const float* bn2_g = (const float*)d_in[11];
    const float* bn2_b = (const float*)d_in[12];
    const float* bn2_m = (const float*)d_in[13];
    const float* bn2_v = (const float*)d_in[14];
    float* out = (float*)d_out;

    __half *vh, *vl, *h1h, *Wh, *Bomh, *B2h;
    float *om, *biasom;
    cudaGetSymbolAddress((void**)&vh,     g_vh);
    cudaGetSymbolAddress((void**)&vl,     g_vl);
    cudaGetSymbolAddress((void**)&h1h,    g_h1h);
    cudaGetSymbolAddress((void**)&om,     g_offmask);
    cudaGetSymbolAddress((void**)&biasom, g_biasom);
    cudaGetSymbolAddress((void**)&Wh,     g_Wh);
    cudaGetSymbolAddress((void**)&Bomh,   g_Bomh);
    cudaGetSymbolAddress((void**)&B2h,    g_B2h);

    const int STAGE1 = 2 * 8704 + 128 * 80;       // 27648 (SPLIT=2, N=128)
    const int STAGE0 = 8704 + 32 * 80;            // 11264 (SPLIT=1, N=32)
    const int STAGE2 = 8704 + 128 * 80;           // 18944 (SPLIT=1, N=128)
    const int smem1 = 2 * STAGE1;                 // 55296
    const int smem0 = 2 * STAGE0;                 // 22528
    const int smem2 = 2 * STAGE2;                 // 37888
    cudaFuncSetAttribute(mma_gemm<32, 1, 0, 1>,
                         cudaFuncAttributeMaxDynamicSharedMemorySize, smem0);
    cudaFuncSetAttribute(mma_gemm<128, 0, 1, 2>,
                         cudaFuncAttributeMaxDynamicSharedMemorySize, smem1);
    cudaFuncSetAttribute(mma_gemm<128, 2, 2, 1>,
                         cudaFuncAttributeMaxDynamicSharedMemorySize, smem2);

    // weight packing
    pack_w_kernel<<<4096, 256>>>(w_reg, w_off, b_off, w_mod, b_mod, w_up);

    // stage 0: offset/mask conv (im2col fused into GEMM A-fill, plain fp16)
    mma_gemm<32, 1, 0, 1><<<dim3(1, 256), 256, smem0>>>(
        x, nullptr, Bomh, om, K1, biasom, nullptr, nullptr, nullptr);

    // stage 1: deform sampling + deform GEMM, 2-term split (+BN1+ReLU -> fp16 h1)
    build_v_kernel<<<dim3(128, 9), 256>>>(x);
    mma_gemm<128, 0, 1, 2><<<dim3(2, 256), 256, smem1>>>(
        vh, vl, Wh, h1h, K1, bn1_g, bn1_b, bn1_m, bn1_v);

    // stage 2: conv-transpose from fp16 h1, plain fp16 (+BN2+ReLU scatter)
    mma_gemm<128, 2, 2, 1><<<dim3(8, 256), 256, smem2>>>(
        h1h, nullptr, B2h, out, K2, bn2_g, bn2_b, bn2_m, bn2_v);
}

// round 10
// speedup vs baseline: 5.2790x; 1.2150x over previous
#include <cuda_runtime.h>
#include <cuda_fp16.h>
#include <math.h>
#include <stdint.h>

#define M_TOT 32768
#define K1 2304
#define K2 1024

// ----------------------------- scratch ---------------------------------------
__device__ __half g_vh[(size_t)K1 * M_TOT];         // deform samples fp16, (K1, M)
__device__ __half g_h1h[(size_t)8 * 256 * 4096];    // stage-1 out, fp16 (b,c,pix)
__device__ float  g_offmask[32u * M_TOT];           // offset/mask conv out (27 used rows)
__device__ __half g_Wh[256 * K1];                   // w_reg fp16 (N,K)
__device__ __half g_Bomh[32 * K1];                  // offset+mask weights (pad 32)
__device__ float  g_biasom[32];
__device__ __half g_B2h[4 * 256 * K2];              // convT per-parity (N,K)

// ----------------------------- helpers ---------------------------------------
__device__ __forceinline__ uint32_t smem_u32(const void* p) {
    uint32_t a;
    asm("{ .reg .u64 t; cvta.to.shared.u64 t, %1; cvt.u32.u64 %0, t; }" : "=r"(a) : "l"(p));
    return a;
}
__device__ __forceinline__ void ldsm4(uint32_t* r, uint32_t addr) {
    asm volatile("ldmatrix.sync.aligned.m8n8.x4.shared.b16 {%0,%1,%2,%3}, [%4];"
                 : "=r"(r[0]), "=r"(r[1]), "=r"(r[2]), "=r"(r[3]) : "r"(addr));
}
__device__ __forceinline__ void ldsm4t(uint32_t* r, uint32_t addr) {
    asm volatile("ldmatrix.sync.aligned.m8n8.x4.trans.shared.b16 {%0,%1,%2,%3}, [%4];"
                 : "=r"(r[0]), "=r"(r[1]), "=r"(r[2]), "=r"(r[3]) : "r"(addr));
}
__device__ __forceinline__ void mma16816(float* c, const uint32_t* a, const uint32_t* b) {
    asm volatile(
        "mma.sync.aligned.m16n8k16.row.col.f32.f16.f16.f32 "
        "{%0,%1,%2,%3}, {%4,%5,%6,%7}, {%8,%9}, {%0,%1,%2,%3};"
        : "+f"(c[0]), "+f"(c[1]), "+f"(c[2]), "+f"(c[3])
        : "r"(a[0]), "r"(a[1]), "r"(a[2]), "r"(a[3]), "r"(b[0]), "r"(b[1]));
}
__device__ __forceinline__ void cp16(uint32_t dst, const void* src) {
    asm volatile("cp.async.ca.shared.global [%0], [%1], 16;" :: "r"(dst), "l"(src));
}
__device__ __forceinline__ void cp_commit() { asm volatile("cp.async.commit_group;"); }
__device__ __forceinline__ void cp_wait0() { asm volatile("cp.async.wait_group 0;"); }
__device__ __forceinline__ void stcs(float* p, float v) {
    asm volatile("st.global.cs.f32 [%0], %1;" :: "l"(p), "f"(v));
}

// ----------------------------- weight packing --------------------------------
__global__ void pack_w_kernel(const float* __restrict__ w_reg, const float* __restrict__ w_off,
                              const float* __restrict__ b_off, const float* __restrict__ w_mod,
                              const float* __restrict__ b_mod, const float* __restrict__ w_up) {
    int i = blockIdx.x * 256 + threadIdx.x;
    if (i < 256 * K1) g_Wh[i] = __float2half(w_reg[i]);
    if (i < 32 * K1) {
        int n = i / K1;
        float v = 0.f;
        if (n < 18) v = w_off[i];
        else if (n < 27) v = w_mod[i - 18 * K1];
        g_Bomh[i] = __float2half(v);
    }
    if (i < 32) g_biasom[i] = (i < 18) ? b_off[i] : ((i < 27) ? b_mod[i - 18] : 0.f);
    if (i < 4 * 256 * K2) {
        int k = i & 1023, n = (i >> 10) & 255, p = i >> 18;
        int c = k >> 2, t = k & 3, ty = t >> 1, tx = t & 1;
        int py = p >> 1, px = p & 1;
        int kh = py ? (ty ? 2 : 0) : (ty ? 3 : 1);
        int kw = px ? (tx ? 2 : 0) : (tx ? 3 : 1);
        g_B2h[i] = __float2half(w_up[(c << 12) + (n << 4) + (kh << 2) + kw]);
    }
}

// ----------------------------- deform sampling -------------------------------
__global__ void build_v_kernel(const float* __restrict__ x) {
    int m = blockIdx.x * 256 + threadIdx.x;
    int k = blockIdx.y;
    int b = m >> 12, pix = m & 4095, h = pix >> 6, w = pix & 63;
    float oy = g_offmask[(size_t)(2 * k) * M_TOT + m];
    float ox = g_offmask[(size_t)(2 * k + 1) * M_TOT + m];
    float mr = g_offmask[(size_t)(18 + k) * M_TOT + m];
    float mask = 2.f / (1.f + expf(-mr));
    int ky = k / 3, kx = k % 3;
    float py = (float)(h - 1 + ky) + oy;
    float px = (float)(w - 1 + kx) + ox;
    float y0f = floorf(py), x0f = floorf(px);
    float wy1 = py - y0f, wx1 = px - x0f;
    float wy0 = 1.f - wy1, wx0 = 1.f - wx1;
    int y0 = (int)y0f, x0 = (int)x0f, y1 = y0 + 1, x1 = x0 + 1;
    bool vy0 = (y0 >= 0 && y0 < 64), vy1 = (y1 >= 0 && y1 < 64);
    bool vx0 = (x0 >= 0 && x0 < 64), vx1 = (x1 >= 0 && x1 < 64);
    int yc0 = min(max(y0, 0), 63), yc1 = min(max(y1, 0), 63);
    int xc0 = min(max(x0, 0), 63), xc1 = min(max(x1, 0), 63);
    int o00 = (yc0 << 6) + xc0, o01 = (yc0 << 6) + xc1;
    int o10 = (yc1 << 6) + xc0, o11 = (yc1 << 6) + xc1;
    float w00 = wy0 * wx0 * ((vy0 && vx0) ? mask : 0.f);
    float w01 = wy0 * wx1 * ((vy0 && vx1) ? mask : 0.f);
    float w10 = wy1 * wx0 * ((vy1 && vx0) ? mask : 0.f);
    float w11 = wy1 * wx1 * ((vy1 && vx1) ? mask : 0.f);
    const float* xb = x + ((size_t)b << 20);
    for (int c = 0; c < 256; c++) {
        const float* xc = xb + (c << 12);
        float v = w00 * xc[o00] + w01 * xc[o01] + w10 * xc[o10] + w11 * xc[o11];
        g_vh[(size_t)(c * 9 + k) * M_TOT + m] = __float2half(v);
    }
}

// ----------------------------- unified HMMA GEMM ------------------------------
// C(M=32768, N) = A(K,M)^T x B(N,K)^T, fp16 in, fp32 accum.
// A SMEM: K-major, 32 k-rows x 128 m-cols, 272B row stride.
// B SMEM: N-major, NTILE n-rows x 32 k-cols, 80B row stride.
// ASRC: 0 = fp16 plane g_vh (cp.async); 1 = im2col gather from x (fp32);
//       2 = tap gather from fp16 h1.
// EPI:  0 = +bias -> (N,M) fp32; 1 = BN+ReLU -> fp16 h1; 2 = BN+ReLU parity scatter.
template <int NTILE, int ASRC, int EPI>
__global__ __launch_bounds__(256, 2) void mma_gemm(
    const void* __restrict__ Asrc, const __half* __restrict__ Bhg,
    void* __restrict__ Cout, int K,
    const float* __restrict__ p0, const float* __restrict__ p1,
    const float* __restrict__ p2, const float* __restrict__ p3) {
    constexpr int WN = (NTILE >= 128) ? 4 : 2;
    constexpr int WM = 8 / WN;
    constexpr int WARP_M = 128 / WM;
    constexpr int WARP_N = NTILE / WN;
    constexpr int MT = WARP_M / 16;
    constexpr int NTG = WARP_N / 16;
    constexpr int NT = NTG * 2;
    constexpr int A_PLANE = 32 * 272;            // 8704
    constexpr int B_PLANE = NTILE * 80;
    constexpr int STAGE = A_PLANE + B_PLANE;
    constexpr int BCH = NTILE * 4;               // cp.async 16B chunks per stage (B)
    constexpr int BJ = (BCH + 255) / 256;

    extern __shared__ char sb[];
    uint32_t sbase = smem_u32(sb);

    int t = threadIdx.x, warp = t >> 5, lane = t & 31;
    int ntile_id, par;
    if (ASRC == 2) { par = blockIdx.x >> 1; ntile_id = blockIdx.x & 1; }
    else { par = 0; ntile_id = blockIdx.x; }
    int nbase = ntile_id * NTILE;
    int m0 = blockIdx.y * 128;
    int py = par >> 1, px = par & 1;

    const __half* Bh = Bhg + ((size_t)par * 256 + nbase) * K;

    int mw = (warp / WN) * WARP_M;
    int nw = (warp % WN) * WARP_N;

    // ldmatrix lane addressing
    int g = lane >> 3;
    int a_k = (lane & 7) + ((g >> 1) << 3);
    int a_moff = (g & 1) << 3;
    uint32_t aBase = (uint32_t)(a_k * 272 + (mw + a_moff) * 2);
    int b_row = (lane & 7) | ((lane >> 4) << 3);
    int b_kh = ((lane >> 3) & 1) << 3;
    uint32_t bBase = (uint32_t)(A_PLANE + (nw + b_row) * 80 + b_kh * 2);

    float acc[MT][NT][4];
#pragma unroll
    for (int i = 0; i < MT; i++)
#pragma unroll
        for (int j = 0; j < NT; j++)
#pragma unroll
            for (int e = 0; e < 4; e++) acc[i][j][e] = 0.f;

    int nch = K >> 5;

    // ---- gather-path A staging registers (held across domma)
    uint32_t wreg[16];

    // ---- A gather: global -> regs for chunk cc (ASRC 1/2 only)
    auto loadA = [&](int cc) {
        int k0 = cc << 5;
#pragma unroll
        for (int j = 0; j < 4; j++) {
            int gi = t + j * 256;           // 1024 groups of 4 m
            int k = gi >> 5, m4 = (gi & 31) << 2;
            int kk = k0 + k;
            if (ASRC == 1) {
                int c = kk / 9, tt = kk - 9 * c, ty = tt / 3, tx = tt - 3 * ty;
                const float* xg = (const float*)Asrc;
#pragma unroll
                for (int e = 0; e < 4; e++) {
                    int gm = m0 + m4 + e;
                    int b = gm >> 12, pix = gm & 4095, ii = pix >> 6, jj = pix & 63;
                    int y = ii + ty - 1, xx = jj + tx - 1;
                    bool ok = ((unsigned)y < 64u) && ((unsigned)xx < 64u);
                    float f = ok ? xg[(((size_t)(b * 256 + c)) << 12) + (y << 6) + xx] : 0.f;
                    wreg[j * 4 + e] = __float_as_uint(f);
                }
            } else if (ASRC == 2) {
                int c = kk >> 2, tt = kk & 3, ty = tt >> 1, tx = tt & 1;
                const __half* hp = (const __half*)Asrc;
#pragma unroll
                for (int e = 0; e < 4; e++) {
                    int gm = m0 + m4 + e;
                    int b = gm >> 12, pix = gm & 4095, ii = pix >> 6, jj = pix & 63;
                    int r = ii + py - ty, cx = jj + px - tx;
                    bool ok = ((unsigned)r < 64u) && ((unsigned)cx < 64u);
                    wreg[j * 4 + e] = ok
                        ? (uint32_t)__half_as_ushort(
                              hp[(((size_t)(b * 256 + c)) << 12) + (r << 6) + cx])
                        : 0u;
                }
            }
        }
    };
    // ---- A store: regs -> SMEM stage s (ASRC 1/2 only)
    auto storeA = [&](int s) {
        char* sA = sb + s * STAGE;
#pragma unroll
        for (int j = 0; j < 4; j++) {
            int gi = t + j * 256;
            int k = gi >> 5, m4 = (gi & 31) << 2;
            int off = k * 272 + m4 * 2;
            if (ASRC == 1) {
                uint32_t hi[4];
#pragma unroll
                for (int e = 0; e < 4; e++)
                    hi[e] = __half_as_ushort(
                        __float2half(__uint_as_float(wreg[j * 4 + e])));
                *(uint2*)(sA + off) =
                    make_uint2(hi[0] | (hi[1] << 16), hi[2] | (hi[3] << 16));
            } else {
                uint32_t* w = &wreg[j * 4];
                *(uint2*)(sA + off) =
                    make_uint2(w[0] | (w[1] << 16), w[2] | (w[3] << 16));
            }
        }
    };
    // ---- A fill via cp.async (ASRC 0 only)
    auto fillA_async = [&](int cc, int s) {
        int k0 = cc << 5;
        const __half* vh = (const __half*)Asrc;
        uint32_t base = sbase + s * STAGE;
#pragma unroll
        for (int j = 0; j < 2; j++) {
            int idx = t + j * 256;          // 512 chunks
            int k = idx >> 4, q = idx & 15;
            const __half* src = vh + (size_t)(k0 + k) * M_TOT + m0 + q * 8;
            cp16(base + k * 272 + q * 16, src);
        }
    };
    // ---- B fill via cp.async
    auto fillB = [&](int cc, int s) {
        int k0 = cc << 5;
        uint32_t base = sbase + s * STAGE + A_PLANE;
#pragma unroll
        for (int j = 0; j < BJ; j++) {
            int idx = t + j * 256;
            if (idx < BCH) {
                int r = idx >> 2, q = idx & 3;
                const __half* src = Bh + (size_t)r * K + k0 + q * 8;
                cp16(base + r * 80 + q * 16, src);
            }
        }
    };
    // ---- MMA on stage s
    auto domma = [&](int s) {
        uint32_t sA0 = sbase + s * STAGE;
#pragma unroll
        for (int ks = 0; ks < 2; ks++) {
            uint32_t aoff = sA0 + aBase + ks * 4352;
            uint32_t boff = sA0 + bBase + ks * 32;
            uint32_t ah[MT][4], bh[NTG][4];
#pragma unroll
            for (int mt = 0; mt < MT; mt++) ldsm4t(ah[mt], aoff + mt * 32);
#pragma unroll
            for (int bg = 0; bg < NTG; bg++) ldsm4(bh[bg], boff + bg * 1280);
#pragma unroll
            for (int mt = 0; mt < MT; mt++)
#pragma unroll
                for (int nt = 0; nt < NT; nt++)
                    mma16816(acc[mt][nt], ah[mt], &bh[nt >> 1][(nt & 1) * 2]);
        }
    };

    // ---- prologue: fill stage 0
    if (ASRC == 0) fillA_async(0, 0);
    else { loadA(0); storeA(0); }
    fillB(0, 0);
    cp_commit();
    cp_wait0();
    __syncthreads();

    for (int c = 0; c < nch; c++) {
        int s = c & 1;
        if (c + 1 < nch) {
            if (ASRC == 0) fillA_async(c + 1, s ^ 1);
            else loadA(c + 1);               // LDGs in flight across domma
            fillB(c + 1, s ^ 1);
            cp_commit();
        }
        domma(s);
        if (ASRC != 0 && c + 1 < nch) storeA(s ^ 1);
        cp_wait0();
        __syncthreads();
    }

    // ---------------- epilogue ----------------
    int gi = lane >> 2, ci = (lane & 3) << 1;
#pragma unroll
    for (int mt = 0; mt < MT; mt++) {
#pragma unroll
        for (int nt = 0; nt < NT; nt++) {
            int nB = nbase + nw + nt * 8 + ci;
            int mA = m0 + mw + mt * 16 + gi;
#pragma unroll
            for (int e = 0; e < 4; e++) {
                int m = mA + ((e >> 1) << 3);
                int nn = nB + (e & 1);
                float v = acc[mt][nt][e];
                if (EPI == 0) {
                    if (nn < 27)
                        ((float*)Cout)[(size_t)nn * M_TOT + m] = v + p0[nn];
                } else {
                    float sc = p0[nn] * rsqrtf(p3[nn] + 1e-5f);
                    float r = fmaxf(v * sc + (p1[nn] - p2[nn] * sc), 0.f);
                    int b = m >> 12, pix = m & 4095;
                    if (EPI == 1) {
                        ((__half*)Cout)[(((size_t)(b * 256 + nn)) << 12) + pix] =
                            __float2half(r);
                    } else {
                        int i2 = pix >> 6, j2 = pix & 63;
                        stcs(&((float*)Cout)[(((size_t)((b * 256 + nn) * 128 +
                              2 * i2 + py)) << 7) + 2 * j2 + px], r);
                    }
                }
            }
        }
    }
}

// -----------------------------------------------------------------------------
extern "C" void kernel_launch(void* const* d_in, const int* in_sizes, int n_in,
                              void* d_out, int out_size) {
    const float* x     = (const float*)d_in[0];
    const float* w_off = (const float*)d_in[1];
    const float* b_off = (const float*)d_in[2];
    const float* w_mod = (const float*)d_in[3];
    const float* b_mod = (const float*)d_in[4];
    const float* w_reg = (const float*)d_in[5];
    const float* bn1_g = (const float*)d_in[6];
    const float* bn1_b = (const float*)d_in[7];
    const float* bn1_m = (const float*)d_in[8];
    const float* bn1_v = (const float*)d_in[9];
    const float* w_up  = (const float*)d_in[10];
    const float* bn2_g = (const float*)d_in[11];
    const float* bn2_b = (const float*)d_in[12];
    const float* bn2_m = (const float*)d_in[13];
    const float* bn2_v = (const float*)d_in[14];
    float* out = (float*)d_out;

    __half *vh, *h1h, *Wh, *Bomh, *B2h;
    float *om, *biasom;
    cudaGetSymbolAddress((void**)&vh,     g_vh);
    cudaGetSymbolAddress((void**)&h1h,    g_h1h);
    cudaGetSymbolAddress((void**)&om,     g_offmask);
    cudaGetSymbolAddress((void**)&biasom, g_biasom);
    cudaGetSymbolAddress((void**)&Wh,     g_Wh);
    cudaGetSymbolAddress((void**)&Bomh,   g_Bomh);
    cudaGetSymbolAddress((void**)&B2h,    g_B2h);

    const int STAGE0 = 8704 + 32 * 80;            // 11264 (N=32)
    const int STAGE128 = 8704 + 128 * 80;         // 18944 (N=128)
    const int smem0 = 2 * STAGE0;                 // 22528
    const int smem128 = 2 * STAGE128;             // 37888
    cudaFuncSetAttribute(mma_gemm<32, 1, 0>,
                         cudaFuncAttributeMaxDynamicSharedMemorySize, smem0);
    cudaFuncSetAttribute(mma_gemm<128, 0, 1>,
                         cudaFuncAttributeMaxDynamicSharedMemorySize, smem128);
    cudaFuncSetAttribute(mma_gemm<128, 2, 2>,
                         cudaFuncAttributeMaxDynamicSharedMemorySize, smem128);

    // weight packing
    pack_w_kernel<<<4096, 256>>>(w_reg, w_off, b_off, w_mod, b_mod, w_up);

    // stage 0: offset/mask conv (im2col fused into GEMM A-fill)
    mma_gemm<32, 1, 0><<<dim3(1, 256), 256, smem0>>>(
        x, Bomh, om, K1, biasom, nullptr, nullptr, nullptr);

    // stage 1: deform sampling + deform GEMM (+BN1+ReLU -> fp16 h1)
    build_v_kernel<<<dim3(128, 9), 256>>>(x);
    mma_gemm<128, 0, 1><<<dim3(2, 256), 256, smem128>>>(
        vh, Wh, h1h, K1, bn1_g, bn1_b, bn1_m, bn1_v);

    // stage 2: conv-transpose from fp16 h1 (+BN2+ReLU scatter)
    mma_gemm<128, 2, 2><<<dim3(8, 256), 256, smem128>>>(
        h1h, B2h, out, K2, bn2_g, bn2_b, bn2_m, bn2_v);
}

// round 11
// speedup vs baseline: 5.5085x; 1.0435x over previous
#include <cuda_runtime.h>
#include <cuda_fp16.h>
#include <math.h>
#include <stdint.h>

#define M_TOT 32768
#define K1 2304
#define K2 1024

// ----------------------------- scratch ---------------------------------------
__device__ __half g_vh[(size_t)K1 * M_TOT];         // deform samples fp16, (K1, M)
__device__ __half g_h1h[(size_t)8 * 256 * 4096];    // stage-1 out, fp16 (b,c,pix)
__device__ float  g_offmask[32u * M_TOT];           // offset/mask conv out (27 used rows)
__device__ __half g_Wh[256 * K1];                   // w_reg fp16 (N,K)
__device__ __half g_Bomh[32 * K1];                  // offset+mask weights (pad 32)
__device__ float  g_biasom[32];
__device__ __half g_B2h[4 * 256 * K2];              // convT per-parity (N,K)

// ----------------------------- helpers ---------------------------------------
__device__ __forceinline__ uint32_t smem_u32(const void* p) {
    uint32_t a;
    asm("{ .reg .u64 t; cvta.to.shared.u64 t, %1; cvt.u32.u64 %0, t; }" : "=r"(a) : "l"(p));
    return a;
}
__device__ __forceinline__ void ldsm4(uint32_t* r, uint32_t addr) {
    asm volatile("ldmatrix.sync.aligned.m8n8.x4.shared.b16 {%0,%1,%2,%3}, [%4];"
                 : "=r"(r[0]), "=r"(r[1]), "=r"(r[2]), "=r"(r[3]) : "r"(addr));
}
__device__ __forceinline__ void ldsm4t(uint32_t* r, uint32_t addr) {
    asm volatile("ldmatrix.sync.aligned.m8n8.x4.trans.shared.b16 {%0,%1,%2,%3}, [%4];"
                 : "=r"(r[0]), "=r"(r[1]), "=r"(r[2]), "=r"(r[3]) : "r"(addr));
}
__device__ __forceinline__ void mma16816(float* c, const uint32_t* a, const uint32_t* b) {
    asm volatile(
        "mma.sync.aligned.m16n8k16.row.col.f32.f16.f16.f32 "
        "{%0,%1,%2,%3}, {%4,%5,%6,%7}, {%8,%9}, {%0,%1,%2,%3};"
        : "+f"(c[0]), "+f"(c[1]), "+f"(c[2]), "+f"(c[3])
        : "r"(a[0]), "r"(a[1]), "r"(a[2]), "r"(a[3]), "r"(b[0]), "r"(b[1]));
}
__device__ __forceinline__ void cp16(uint32_t dst, const void* src) {
    asm volatile("cp.async.ca.shared.global [%0], [%1], 16;" :: "r"(dst), "l"(src));
}
__device__ __forceinline__ void cp_commit() { asm volatile("cp.async.commit_group;"); }
__device__ __forceinline__ void cp_wait0() { asm volatile("cp.async.wait_group 0;"); }
__device__ __forceinline__ void stcs(float* p, float v) {
    asm volatile("st.global.cs.f32 [%0], %1;" :: "l"(p), "f"(v));
}

// ----------------------------- weight packing --------------------------------
__global__ void pack_w_kernel(const float* __restrict__ w_reg, const float* __restrict__ w_off,
                              const float* __restrict__ b_off, const float* __restrict__ w_mod,
                              const float* __restrict__ b_mod, const float* __restrict__ w_up) {
    int i = blockIdx.x * 256 + threadIdx.x;
    if (i < 256 * K1) g_Wh[i] = __float2half(w_reg[i]);
    if (i < 32 * K1) {
        int n = i / K1;
        float v = 0.f;
        if (n < 18) v = w_off[i];
        else if (n < 27) v = w_mod[i - 18 * K1];
        g_Bomh[i] = __float2half(v);
    }
    if (i < 32) g_biasom[i] = (i < 18) ? b_off[i] : ((i < 27) ? b_mod[i - 18] : 0.f);
    if (i < 4 * 256 * K2) {
        int k = i & 1023, n = (i >> 10) & 255, p = i >> 18;
        int c = k >> 2, t = k & 3, ty = t >> 1, tx = t & 1;
        int py = p >> 1, px = p & 1;
        int kh = py ? (ty ? 2 : 0) : (ty ? 3 : 1);
        int kw = px ? (tx ? 2 : 0) : (tx ? 3 : 1);
        g_B2h[i] = __float2half(w_up[(c << 12) + (n << 4) + (kh << 2) + kw]);
    }
}

// ----------------------------- deform sampling -------------------------------
__global__ void build_v_kernel(const float* __restrict__ x) {
    int m = blockIdx.x * 256 + threadIdx.x;
    int k = blockIdx.y;
    int b = m >> 12, pix = m & 4095, h = pix >> 6, w = pix & 63;
    float oy = g_offmask[(size_t)(2 * k) * M_TOT + m];
    float ox = g_offmask[(size_t)(2 * k + 1) * M_TOT + m];
    float mr = g_offmask[(size_t)(18 + k) * M_TOT + m];
    float mask = 2.f / (1.f + expf(-mr));
    int ky = k / 3, kx = k % 3;
    float py = (float)(h - 1 + ky) + oy;
    float px = (float)(w - 1 + kx) + ox;
    float y0f = floorf(py), x0f = floorf(px);
    float wy1 = py - y0f, wx1 = px - x0f;
    float wy0 = 1.f - wy1, wx0 = 1.f - wx1;
    int y0 = (int)y0f, x0 = (int)x0f, y1 = y0 + 1, x1 = x0 + 1;
    bool vy0 = (y0 >= 0 && y0 < 64), vy1 = (y1 >= 0 && y1 < 64);
    bool vx0 = (x0 >= 0 && x0 < 64), vx1 = (x1 >= 0 && x1 < 64);
    int yc0 = min(max(y0, 0), 63), yc1 = min(max(y1, 0), 63);
    int xc0 = min(max(x0, 0), 63), xc1 = min(max(x1, 0), 63);
    int o00 = (yc0 << 6) + xc0, o01 = (yc0 << 6) + xc1;
    int o10 = (yc1 << 6) + xc0, o11 = (yc1 << 6) + xc1;
    float w00 = wy0 * wx0 * ((vy0 && vx0) ? mask : 0.f);
    float w01 = wy0 * wx1 * ((vy0 && vx1) ? mask : 0.f);
    float w10 = wy1 * wx0 * ((vy1 && vx0) ? mask : 0.f);
    float w11 = wy1 * wx1 * ((vy1 && vx1) ? mask : 0.f);
    const float* xb = x + ((size_t)b << 20);
    for (int c = 0; c < 256; c++) {
        const float* xc = xb + (c << 12);
        float v = w00 * xc[o00] + w01 * xc[o01] + w10 * xc[o10] + w11 * xc[o11];
        g_vh[(size_t)(c * 9 + k) * M_TOT + m] = __float2half(v);
    }
}

// ----------------------------- unified HMMA GEMM ------------------------------
// C(M=32768, N) = A(K,M)^T x B(N,K)^T, fp16 in, fp32 accum.  K-chunk = 64.
// A SMEM: K-major, 64 k-rows x 128 m-cols, 272B row stride.
// B SMEM: N-major, NTILE n-rows x 64 k-cols, 144B row stride.
// ASRC: 0 = fp16 plane g_vh (cp.async); 1 = im2col gather from x (fp32);
//       2 = tap gather from fp16 h1.
// EPI:  0 = +bias -> (N,M) fp32; 1 = BN+ReLU -> fp16 h1; 2 = BN+ReLU parity scatter.
template <int NTILE, int ASRC, int EPI>
__global__ __launch_bounds__(256, 2) void mma_gemm(
    const void* __restrict__ Asrc, const __half* __restrict__ Bhg,
    void* __restrict__ Cout, int K,
    const float* __restrict__ p0, const float* __restrict__ p1,
    const float* __restrict__ p2, const float* __restrict__ p3) {
    constexpr int WN = (NTILE >= 128) ? 4 : 2;
    constexpr int WM = 8 / WN;
    constexpr int WARP_M = 128 / WM;
    constexpr int WARP_N = NTILE / WN;
    constexpr int MT = WARP_M / 16;
    constexpr int NTG = WARP_N / 16;
    constexpr int NT = NTG * 2;
    constexpr int A_PLANE = 64 * 272;            // 17408
    constexpr int B_PLANE = NTILE * 144;
    constexpr int STAGE = A_PLANE + B_PLANE;
    constexpr int BCH = NTILE * 8;               // cp.async 16B chunks per stage (B)
    constexpr int BJ = (BCH + 255) / 256;

    extern __shared__ char sb[];
    uint32_t sbase = smem_u32(sb);

    int t = threadIdx.x, warp = t >> 5, lane = t & 31;
    int ntile_id, par;
    if (ASRC == 2) { par = blockIdx.x >> 1; ntile_id = blockIdx.x & 1; }
    else { par = 0; ntile_id = blockIdx.x; }
    int nbase = ntile_id * NTILE;
    int m0 = blockIdx.y * 128;
    int py = par >> 1, px = par & 1;

    const __half* Bh = Bhg + ((size_t)par * 256 + nbase) * K;

    int mw = (warp / WN) * WARP_M;
    int nw = (warp % WN) * WARP_N;

    // ldmatrix lane addressing
    int g = lane >> 3;
    int a_k = (lane & 7) + ((g >> 1) << 3);
    int a_moff = (g & 1) << 3;
    uint32_t aBase = (uint32_t)(a_k * 272 + (mw + a_moff) * 2);
    int b_row = (lane & 7) | ((lane >> 4) << 3);
    int b_kh = ((lane >> 3) & 1) << 3;
    uint32_t bBase = (uint32_t)(A_PLANE + (nw + b_row) * 144 + b_kh * 2);

    float acc[MT][NT][4];
#pragma unroll
    for (int i = 0; i < MT; i++)
#pragma unroll
        for (int j = 0; j < NT; j++)
#pragma unroll
            for (int e = 0; e < 4; e++) acc[i][j][e] = 0.f;

    int nch = K >> 6;

    // ---- A fill into stage s for chunk cc
    auto fillA = [&](int cc, int s) {
        int k0 = cc << 6;
        if (ASRC == 0) {
            const __half* vh = (const __half*)Asrc;
            uint32_t base = sbase + s * STAGE;
#pragma unroll
            for (int j = 0; j < 4; j++) {
                int idx = t + j * 256;          // 1024 chunks
                int k = idx >> 4, q = idx & 15;
                const __half* src = vh + (size_t)(k0 + k) * M_TOT + m0 + q * 8;
                cp16(base + k * 272 + q * 16, src);
            }
        } else {
            char* sA = sb + s * STAGE;
#pragma unroll
            for (int j = 0; j < 8; j++) {
                int gi = t + j * 256;           // 2048 groups of 4 m
                int k = gi >> 5, m4 = (gi & 31) << 2;
                int kk = k0 + k;
                int off = k * 272 + m4 * 2;
                if (ASRC == 1) {
                    int c = kk / 9, tt = kk - 9 * c, ty = tt / 3, tx = tt - 3 * ty;
                    const float* xg = (const float*)Asrc;
                    uint32_t hi[4];
#pragma unroll
                    for (int e = 0; e < 4; e++) {
                        int gm = m0 + m4 + e;
                        int b = gm >> 12, pix = gm & 4095, ii = pix >> 6, jj = pix & 63;
                        int y = ii + ty - 1, xx = jj + tx - 1;
                        bool ok = ((unsigned)y < 64u) && ((unsigned)xx < 64u);
                        float f = ok ? xg[(((size_t)(b * 256 + c)) << 12) + (y << 6) + xx] : 0.f;
                        hi[e] = __half_as_ushort(__float2half(f));
                    }
                    *(uint2*)(sA + off) =
                        make_uint2(hi[0] | (hi[1] << 16), hi[2] | (hi[3] << 16));
                } else {
                    int c = kk >> 2, tt = kk & 3, ty = tt >> 1, tx = tt & 1;
                    const __half* hp = (const __half*)Asrc;
                    uint32_t w[4];
#pragma unroll
                    for (int e = 0; e < 4; e++) {
                        int gm = m0 + m4 + e;
                        int b = gm >> 12, pix = gm & 4095, ii = pix >> 6, jj = pix & 63;
                        int r = ii + py - ty, cx = jj + px - tx;
                        bool ok = ((unsigned)r < 64u) && ((unsigned)cx < 64u);
                        w[e] = ok
                            ? (uint32_t)__half_as_ushort(
                                  hp[(((size_t)(b * 256 + c)) << 12) + (r << 6) + cx])
                            : 0u;
                    }
                    *(uint2*)(sA + off) =
                        make_uint2(w[0] | (w[1] << 16), w[2] | (w[3] << 16));
                }
            }
        }
    };
    // ---- B fill via cp.async
    auto fillB = [&](int cc, int s) {
        int k0 = cc << 6;
        uint32_t base = sbase + s * STAGE + A_PLANE;
#pragma unroll
        for (int j = 0; j < BJ; j++) {
            int idx = t + j * 256;
            if (idx < BCH) {
                int r = idx >> 3, q = idx & 7;
                const __half* src = Bh + (size_t)r * K + k0 + q * 8;
                cp16(base + r * 144 + q * 16, src);
            }
        }
    };
    // ---- MMA on stage s (4 k16 steps)
    auto domma = [&](int s) {
        uint32_t sA0 = sbase + s * STAGE;
#pragma unroll
        for (int ks = 0; ks < 4; ks++) {
            uint32_t aoff = sA0 + aBase + ks * 4352;
            uint32_t boff = sA0 + bBase + ks * 32;
            uint32_t ah[MT][4], bh[NTG][4];
#pragma unroll
            for (int mt = 0; mt < MT; mt++) ldsm4t(ah[mt], aoff + mt * 32);
#pragma unroll
            for (int bg = 0; bg < NTG; bg++) ldsm4(bh[bg], boff + bg * 2304);
#pragma unroll
            for (int mt = 0; mt < MT; mt++)
#pragma unroll
                for (int nt = 0; nt < NT; nt++)
                    mma16816(acc[mt][nt], ah[mt], &bh[nt >> 1][(nt & 1) * 2]);
        }
    };

    // ---- prologue: fill stage 0
    fillA(0, 0);
    fillB(0, 0);
    cp_commit();
    cp_wait0();
    __syncthreads();

    for (int c = 0; c < nch; c++) {
        int s = c & 1;
        if (c + 1 < nch) {
            fillA(c + 1, s ^ 1);
            fillB(c + 1, s ^ 1);
            cp_commit();
        }
        domma(s);
        cp_wait0();
        __syncthreads();
    }

    // ---------------- epilogue ----------------
    int gi = lane >> 2, ci = (lane & 3) << 1;
#pragma unroll
    for (int mt = 0; mt < MT; mt++) {
#pragma unroll
        for (int nt = 0; nt < NT; nt++) {
            int nB = nbase + nw + nt * 8 + ci;
            int mA = m0 + mw + mt * 16 + gi;
#pragma unroll
            for (int e = 0; e < 4; e++) {
                int m = mA + ((e >> 1) << 3);
                int nn = nB + (e & 1);
                float v = acc[mt][nt][e];
                if (EPI == 0) {
                    if (nn < 27)
                        ((float*)Cout)[(size_t)nn * M_TOT + m] = v + p0[nn];
                } else {
                    float sc = p0[nn] * rsqrtf(p3[nn] + 1e-5f);
                    float r = fmaxf(v * sc + (p1[nn] - p2[nn] * sc), 0.f);
                    int b = m >> 12, pix = m & 4095;
                    if (EPI == 1) {
                        ((__half*)Cout)[(((size_t)(b * 256 + nn)) << 12) + pix] =
                            __float2half(r);
                    } else {
                        int i2 = pix >> 6, j2 = pix & 63;
                        stcs(&((float*)Cout)[(((size_t)((b * 256 + nn) * 128 +
                              2 * i2 + py)) << 7) + 2 * j2 + px], r);
                    }
                }
            }
        }
    }
}

// -----------------------------------------------------------------------------
extern "C" void kernel_launch(void* const* d_in, const int* in_sizes, int n_in,
                              void* d_out, int out_size) {
    const float* x     = (const float*)d_in[0];
    const float* w_off = (const float*)d_in[1];
    const float* b_off = (const float*)d_in[2];
    const float* w_mod = (const float*)d_in[3];
    const float* b_mod = (const float*)d_in[4];
    const float* w_reg = (const float*)d_in[5];
    const float* bn1_g = (const float*)d_in[6];
    const float* bn1_b = (const float*)d_in[7];
    const float* bn1_m = (const float*)d_in[8];
    const float* bn1_v = (const float*)d_in[9];
    const float* w_up  = (const float*)d_in[10];
    const float* bn2_g = (const float*)d_in[11];
    const float* bn2_b = (const float*)d_in[12];
    const float* bn2_m = (const float*)d_in[13];
    const float* bn2_v = (const float*)d_in[14];
    float* out = (float*)d_out;

    __half *vh, *h1h, *Wh, *Bomh, *B2h;
    float *om, *biasom;
    cudaGetSymbolAddress((void**)&vh,     g_vh);
    cudaGetSymbolAddress((void**)&h1h,    g_h1h);
    cudaGetSymbolAddress((void**)&om,     g_offmask);
    cudaGetSymbolAddress((void**)&biasom, g_biasom);
    cudaGetSymbolAddress((void**)&Wh,     g_Wh);
    cudaGetSymbolAddress((void**)&Bomh,   g_Bomh);
    cudaGetSymbolAddress((void**)&B2h,    g_B2h);

    const int STAGE0 = 17408 + 32 * 144;          // 22016 (N=32)
    const int STAGE128 = 17408 + 128 * 144;       // 35840 (N=128)
    const int smem0 = 2 * STAGE0;                 // 44032
    const int smem128 = 2 * STAGE128;             // 71680
    cudaFuncSetAttribute(mma_gemm<32, 1, 0>,
                         cudaFuncAttributeMaxDynamicSharedMemorySize, smem0);
    cudaFuncSetAttribute(mma_gemm<128, 0, 1>,
                         cudaFuncAttributeMaxDynamicSharedMemorySize, smem128);
    cudaFuncSetAttribute(mma_gemm<128, 2, 2>,
                         cudaFuncAttributeMaxDynamicSharedMemorySize, smem128);

    // weight packing
    pack_w_kernel<<<4096, 256>>>(w_reg, w_off, b_off, w_mod, b_mod, w_up);

    // stage 0: offset/mask conv (im2col fused into GEMM A-fill)
    mma_gemm<32, 1, 0><<<dim3(1, 256), 256, smem0>>>(
        x, Bomh, om, K1, biasom, nullptr, nullptr, nullptr);

    // stage 1: deform sampling + deform GEMM (+BN1+ReLU -> fp16 h1)
    build_v_kernel<<<dim3(128, 9), 256>>>(x);
    mma_gemm<128, 0, 1><<<dim3(2, 256), 256, smem128>>>(
        vh, Wh, h1h, K1, bn1_g, bn1_b, bn1_m, bn1_v);

    // stage 2: conv-transpose from fp16 h1 (+BN2+ReLU scatter)
    mma_gemm<128, 2, 2><<<dim3(8, 256), 256, smem128>>>(
        h1h, B2h, out, K2, bn2_g, bn2_b, bn2_m, bn2_v);
}